// round 3
// baseline (speedup 1.0000x reference)
#include <cuda_runtime.h>
#include <math.h>

#define NUL 2000
#define NUV 1500
#define EPSF 1e-6f

// Complex principal sqrt of (x + iy); also returns m = |x+iy|.
__device__ __forceinline__ void csqrtf_m(float x, float y, float &sx, float &sy, float &m)
{
    m = sqrtf(fmaf(x, x, y * y));
    if (x >= 0.0f) {
        float t = sqrtf(0.5f * (m + x));
        sx = t;
        sy = (t > 0.0f) ? (0.5f * __fdividef(y, t)) : 0.0f;
    } else {
        float t = sqrtf(0.5f * (m - x));
        sy = copysignf(t, y);
        sx = (t > 0.0f) ? (0.5f * __fdividef(fabsf(y), t)) : 0.0f;
    }
}

__global__ void __launch_bounds__(256)
adsbh_kernel(const float* __restrict__ A,
             const float* __restrict__ Bc,
             const float* __restrict__ ZS,
             float* __restrict__ out, int B)
{
    const int warp = blockIdx.x * (blockDim.x >> 5) + (threadIdx.x >> 5);
    const int lane = threadIdx.x & 31;
    if (warp >= B) return;

    const float a1 = A[0], a2 = A[1], a3 = A[2], a4 = A[3], a5 = A[4];
    const float b1 = Bc[0], b2 = Bc[1], b3 = Bc[2], b4 = Bc[3], b5 = Bc[4];

    const float zsv = ZS[warp];
    const float zs2 = zsv * zsv;
    const float zs4 = zs2 * zs2;

    // P_a(zs), f(zs)
    const float Pazs  = zsv * fmaf(zsv, fmaf(zsv, fmaf(zsv, fmaf(zsv, a5, a4), a3), a2), a1);
    const float e_pazs = expf(Pazs);
    const float fzs    = (1.0f - zs4) * e_pazs;
    const float epz4   = e_pazs * zs4;

    // A_i * zs^i for the stable delta-poly
    const float Az1 = a1 * zsv;
    const float Az2 = a2 * zs2;
    const float Az3 = a3 * zs2 * zsv;
    const float Az4 = a4 * zs4;
    const float Az5 = a5 * zs4 * zsv;

    // ------------------------- L integral (Nu = 2000) -------------------------
    const double hL = (1.0 - 2.0e-6) / (double)(NUL - 1);
    float accLr = 0.0f, accLi = 0.0f;

    for (int k = lane; k < NUL; k += 32) {
        const double ud  = 1.0e-6 + (double)k * hL;
        const float  u   = (float)ud;
        const float  omu = (float)(1.0 - ud);

        const float z   = zsv * u;
        const float z2  = z * z;
        const float z4  = z2 * z2;
        const float omz4 = 1.0f - z4;

        const float u2 = u * u, u3 = u2 * u, u4 = u2 * u2;
        const float s2 = 1.0f + u, s3 = s2 + u2, s4 = s3 + u3, s5 = s4 + u4;
        const float sumA = fmaf(Az5, s5, fmaf(Az4, s4, fmaf(Az3, s3, fmaf(Az2, s2, Az1))));
        const float dPa  = -omu * sumA;                 // P_a(z) - P_a(zs), stable
        const float Em   = expm1f(dPa);
        const float om_u4 = omu * s4;                   // 1 - u^4, stable

        const float oEm = omz4 * Em;
        const float fz  = e_pazs * (omz4 + oEm);        // f(a, z)
        const float S   = epz4 * (oEm + om_u4);         // zs^4 f(z) - z^4 f(zs), stable

        const float N    = zs4 * fz;
        const float R    = fmaf(z4, fzs, EPSF);
        const float rden = __fdividef(1.0f, fmaf(R, R, 1e-12f));
        // denom = N/(R + i*eps) - 1 + eps*(1+i)
        const float Dre = fmaf(R, S - EPSF, -1e-12f) * rden + EPSF;
        const float Dim = EPSF - N * EPSF * rden;

        float sx, sy, m;
        csqrtf_m(Dre, Dim, sx, sy, m);

        // sqrt(g(b,z)) = exp(P_b(z)/2) / sqrt(1 - z^4)
        const float Pb = z * fmaf(z, fmaf(z, fmaf(z, fmaf(z, b5, b4), b3), b2), b1);
        const float sqrt_gz = __expf(0.5f * Pb) * rsqrtf(omz4);

        // integrand = sqrt_gz / sqrt(D) = sqrt_gz * conj(sqrtD) / |D|
        const float r = __fdividef(sqrt_gz, m);
        const float wk = (k == 0 || k == NUL - 1) ? 0.5f : 1.0f;
        accLr = fmaf(wk, r * sx, accLr);
        accLi = fmaf(wk, -r * sy, accLi);
    }

    // ------------------------- V integral (Nu = 1500) -------------------------
    const double hV = (1.0 - 2.0e-6) / (double)(NUV - 1);
    float accVr = 0.0f, accVi = 0.0f;

    for (int k = lane; k < NUV; k += 32) {
        const double ud  = 1.0e-6 + (double)k * hV;
        const float  u   = (float)ud;
        const float  omu = (float)(1.0 - ud);

        const float z   = zsv * u;
        const float z2  = z * z;
        const float z4  = z2 * z2;
        const float omz4 = 1.0f - z4;

        const float u2 = u * u, u3 = u2 * u, u4 = u2 * u2;
        const float s2 = 1.0f + u, s3 = s2 + u2, s4 = s3 + u3, s5 = s4 + u4;
        const float sumA = fmaf(Az5, s5, fmaf(Az4, s4, fmaf(Az3, s3, fmaf(Az2, s2, Az1))));
        const float dPa  = -omu * sumA;
        const float Em   = expm1f(dPa);
        const float om_u4 = omu * s4;

        const float oEm = omz4 * Em;
        const float fz  = e_pazs * (omz4 + oEm);
        const float S   = epz4 * (oEm + om_u4);

        const float M    = z4 * fzs;
        const float Rp   = fmaf(zs4, fz, EPSF);
        const float rden = __fdividef(1.0f, fmaf(Rp, Rp, 1e-12f));
        // inner = 1 - M/(Rp + i*eps) + eps*(1+i)
        const float ire = fmaf(Rp, S + EPSF, 1e-12f) * rden + EPSF;
        const float iim = EPSF + M * EPSF * rden;

        float sx, sy, m;
        csqrtf_m(ire, iim, sx, sy, m);

        // sqrt(f*g) = exp((P_a(z) + P_b(z)) / 2)
        const float Pb  = z * fmaf(z, fmaf(z, fmaf(z, fmaf(z, b5, b4), b3), b2), b1);
        const float Paz = Pazs + dPa;
        const float Ep  = __expf(0.5f * (Paz + Pb));

        // term = Ep / sqrt(inner) - 1 = Ep*conj(sq)/|inner| - 1
        const float t   = __fdividef(Ep, m);
        const float tre = fmaf(t, sx, -1.0f);
        const float tim = -t * sy;

        // integrand = term / (z^2 + eps*(1+i))
        const float cr  = fmaf(z, z, EPSF);
        const float rc2 = __fdividef(1.0f, fmaf(cr, cr, 1e-12f));
        const float Ire = fmaf(tre, cr, tim * EPSF) * rc2;
        const float Iim = fmaf(tim, cr, -tre * EPSF) * rc2;

        const float wk = (k == 0 || k == NUV - 1) ? 0.5f : 1.0f;
        accVr = fmaf(wk, Ire, accVr);
        accVi = fmaf(wk, Iim, accVi);
    }

    // ------------------------- warp reduction + writeback -------------------------
    #pragma unroll
    for (int o = 16; o > 0; o >>= 1) {
        accLr += __shfl_xor_sync(0xFFFFFFFFu, accLr, o);
        accLi += __shfl_xor_sync(0xFFFFFFFFu, accLi, o);
        accVr += __shfl_xor_sync(0xFFFFFFFFu, accVr, o);
        accVi += __shfl_xor_sync(0xFFFFFFFFu, accVi, o);
    }

    if (lane == 0) {
        const float sL = (float)((2.0 / M_PI) * hL) * zsv;
        const float sV = (float)(2.0 * M_PI * hV) * zsv;
        const float vdisc = (float)(2.0 * M_PI) / zsv;
        out[0 * B + warp] = accLr * sL;
        out[1 * B + warp] = accLi * sL;
        out[2 * B + warp] = accVr * sV - vdisc;
        out[3 * B + warp] = accVi * sV;
    }
}

extern "C" void kernel_launch(void* const* d_in, const int* in_sizes, int n_in,
                              void* d_out, int out_size)
{
    const float* a  = (const float*)d_in[0];
    const float* b  = (const float*)d_in[1];
    const float* zs = (const float*)d_in[2];
    float* out = (float*)d_out;
    const int B = in_sizes[2];

    const int warps_per_block = 256 / 32;
    const int blocks = (B + warps_per_block - 1) / warps_per_block;
    adsbh_kernel<<<blocks, 256>>>(a, b, zs, out, B);
}

// round 6
// speedup vs baseline: 1.1059x; 1.1059x over previous
#include <cuda_runtime.h>
#include <math.h>

#define NUL 2000
#define NUV 1500
#define EPSF 1e-6f
#define EPS2 1e-12f

// Branchless pieces of w^{-1/2} for w = x+iy:
// returns sx,sy with sqrt(w) = sx + i*sy (principal), and rm = 1/|w|.
__device__ __forceinline__ void cinvsqrt_parts(float x, float y,
                                               float &sx, float &sy, float &rm)
{
    float q  = fmaf(x, x, y * y);
    rm       = rsqrtf(q);          // 1/|w|
    float m  = q * rm;             // |w|
    float tt = fmaf(0.5f, m, 0.5f * fabsf(x));
    float it = rsqrtf(tt);
    float tb = tt * it;            // sqrt((|w|+|x|)/2)
    if (x >= 0.0f) { sx = tb;                  sy = 0.5f * y * it; }
    else           { sx = 0.5f * fabsf(y) * it; sy = copysignf(tb, y); }
}

// expm1 with branchless select: poly for small |x|, expf-1 otherwise.
__device__ __forceinline__ float fast_expm1(float x, float ex)
{
    float p = fmaf(x, 8.3333333e-3f, 4.1666667e-2f);
    p = fmaf(p, x, 1.6666667e-1f);
    p = fmaf(p, x, 0.5f);
    p = fmaf(p, x, 1.0f);
    float poly = x * p;
    return (fabsf(x) < 0.2f) ? poly : (ex - 1.0f);
}

__global__ void __launch_bounds__(256)
adsbh_kernel(const float* __restrict__ A,
             const float* __restrict__ Bc,
             const float* __restrict__ ZS,
             float* __restrict__ out, int B)
{
    __shared__ float red[8][4];

    const int w    = threadIdx.x >> 5;
    const int lane = threadIdx.x & 31;
    const int slot = w >> 1;          // 4 zs per block
    const int par  = w & 1;           // 2 warps per zs
    const int zi   = blockIdx.x * 4 + slot;
    const bool valid = (zi < B);

    const float a1 = A[0], a2 = A[1], a3 = A[2], a4 = A[3], a5 = A[4];
    const float b1 = Bc[0], b2 = Bc[1], b3 = Bc[2], b4 = Bc[3], b5 = Bc[4];

    const float zsv = valid ? ZS[zi] : 0.5f;
    const float zs2 = zsv * zsv;
    const float zs4 = zs2 * zs2;

    const float Pazs   = zsv * fmaf(zsv, fmaf(zsv, fmaf(zsv, fmaf(zsv, a5, a4), a3), a2), a1);
    const float e_pazs = expf(Pazs);
    const float fzs    = (1.0f - zs4) * e_pazs;
    const float epz4   = e_pazs * zs4;

    const float Az1 = a1 * zsv;
    const float Az2 = a2 * zs2;
    const float Az3 = a3 * zs2 * zsv;
    const float Az4 = a4 * zs4;
    const float Az5 = a5 * zs4 * zsv;

    const double hL = (1.0 - 2.0e-6) / (double)(NUL - 1);
    const double hV = (1.0 - 2.0e-6) / (double)(NUV - 1);

    float accLr = 0.0f, accLi = 0.0f, accVr = 0.0f, accVi = 0.0f;

    int kL = lane + 32 * par;
    int kV = kL;

    while (kL < NUL || kV < NUV) {
        // ============================ L point ============================
        if (kL < NUL) {
            const double ud  = 1.0e-6 + (double)kL * hL;
            const float  u   = (float)ud;
            const float  omu = (float)(1.0 - ud);

            float s2 = u + 1.0f;
            float s3 = fmaf(s2, u, 1.0f);
            float s4 = fmaf(s3, u, 1.0f);
            float s5 = fmaf(s4, u, 1.0f);
            const float sumA = fmaf(Az5, s5, fmaf(Az4, s4, fmaf(Az3, s3, fmaf(Az2, s2, Az1))));
            const float dPa  = -omu * sumA;
            const float ex   = __expf(dPa);
            const float Em   = fast_expm1(dPa, ex);

            const float z    = zsv * u;
            const float z2   = z * z;
            const float z4   = z2 * z2;
            const float omz4 = 1.0f - z4;

            const float oEm   = omz4 * Em;
            const float om_u4 = omu * s4;                 // 1 - u^4, stable
            const float S     = epz4 * (oEm + om_u4);     // zs^4 f(z) - z^4 f(zs)
            const float N     = epz4 * (omz4 + oEm);      // zs^4 f(z)
            const float R     = fmaf(z4, fzs, EPSF);
            const float rden  = __fdividef(1.0f, fmaf(R, R, EPS2));
            const float Dre   = fmaf(fmaf(R, S - EPSF, -EPS2), rden, EPSF);
            const float Dim   = fmaf(-(N * rden), EPSF, EPSF);

            float sx, sy, rm;
            cinvsqrt_parts(Dre, Dim, sx, sy, rm);

            const float Pb = z * fmaf(z, fmaf(z, fmaf(z, fmaf(z, b5, b4), b3), b2), b1);
            const float r  = __expf(0.5f * Pb) * rsqrtf(omz4) * rm;
            const float wk = (kL == 0 || kL == NUL - 1) ? 0.5f : 1.0f;
            const float rr = r * wk;
            accLr = fmaf(rr,  sx, accLr);
            accLi = fmaf(rr, -sy, accLi);
        }

        // ============================ V point ============================
        if (kV < NUV) {
            const double ud  = 1.0e-6 + (double)kV * hV;
            const float  u   = (float)ud;
            const float  omu = (float)(1.0 - ud);

            float s2 = u + 1.0f;
            float s3 = fmaf(s2, u, 1.0f);
            float s4 = fmaf(s3, u, 1.0f);
            float s5 = fmaf(s4, u, 1.0f);
            const float sumA = fmaf(Az5, s5, fmaf(Az4, s4, fmaf(Az3, s3, fmaf(Az2, s2, Az1))));
            const float dPa  = -omu * sumA;
            const float ex   = __expf(dPa);
            const float Em   = fast_expm1(dPa, ex);

            const float z    = zsv * u;
            const float z2   = z * z;
            const float z4   = z2 * z2;
            const float omz4 = 1.0f - z4;

            const float oEm   = omz4 * Em;
            const float om_u4 = omu * s4;
            const float S     = epz4 * (oEm + om_u4);
            const float N     = epz4 * (omz4 + oEm);      // zs^4 f(z)
            const float Rp    = N + EPSF;
            const float M     = z4 * fzs;
            const float rden  = __fdividef(1.0f, fmaf(Rp, Rp, EPS2));
            const float ire   = fmaf(fmaf(Rp, S + EPSF, EPS2), rden, EPSF);
            const float iim   = fmaf(M * rden, EPSF, EPSF);

            float sx, sy, rm;
            cinvsqrt_parts(ire, iim, sx, sy, rm);

            const float Pb = z * fmaf(z, fmaf(z, fmaf(z, fmaf(z, b5, b4), b3), b2), b1);
            const float Ep = __expf(0.5f * (Pazs + dPa + Pb));

            const float t   = Ep * rm;
            const float tre = fmaf(t, sx, -1.0f);
            const float tim = -t * sy;

            const float cr  = fmaf(z, z, EPSF);
            const float rc2 = __fdividef(1.0f, fmaf(cr, cr, EPS2));
            const float Ire = fmaf(tre, cr,  tim * EPSF) * rc2;
            const float Iim = fmaf(tim, cr, -tre * EPSF) * rc2;

            const float wk = (kV == 0 || kV == NUV - 1) ? 0.5f : 1.0f;
            accVr = fmaf(wk, Ire, accVr);
            accVi = fmaf(wk, Iim, accVi);
        }

        kL += 64;
        kV += 64;
    }

    // warp-internal reduction
    #pragma unroll
    for (int o = 16; o > 0; o >>= 1) {
        accLr += __shfl_xor_sync(0xFFFFFFFFu, accLr, o);
        accLi += __shfl_xor_sync(0xFFFFFFFFu, accLi, o);
        accVr += __shfl_xor_sync(0xFFFFFFFFu, accVr, o);
        accVi += __shfl_xor_sync(0xFFFFFFFFu, accVi, o);
    }
    if (lane == 0) {
        red[w][0] = accLr;
        red[w][1] = accLi;
        red[w][2] = accVr;
        red[w][3] = accVi;
    }
    __syncthreads();

    // combine the warp pair for each zs and write out
    if (threadIdx.x < 4) {
        const int zo = blockIdx.x * 4 + threadIdx.x;
        if (zo < B) {
            const int e = 2 * threadIdx.x;
            const float Lr = red[e][0] + red[e + 1][0];
            const float Li = red[e][1] + red[e + 1][1];
            const float Vr = red[e][2] + red[e + 1][2];
            const float Vi = red[e][3] + red[e + 1][3];

            const float z0 = ZS[zo];
            const double hLd = (1.0 - 2.0e-6) / (double)(NUL - 1);
            const double hVd = (1.0 - 2.0e-6) / (double)(NUV - 1);
            const float sL = (float)((2.0 / M_PI) * hLd) * z0;
            const float sV = (float)(2.0 * M_PI * hVd) * z0;
            const float vdisc = (float)(2.0 * M_PI) / z0;

            out[0 * B + zo] = Lr * sL;
            out[1 * B + zo] = Li * sL;
            out[2 * B + zo] = Vr * sV - vdisc;
            out[3 * B + zo] = Vi * sV;
        }
    }
}

extern "C" void kernel_launch(void* const* d_in, const int* in_sizes, int n_in,
                              void* d_out, int out_size)
{
    const float* a  = (const float*)d_in[0];
    const float* b  = (const float*)d_in[1];
    const float* zs = (const float*)d_in[2];
    float* out = (float*)d_out;
    const int B = in_sizes[2];

    const int blocks = (B + 3) / 4;   // 4 zs per block (8 warps, 2 per zs)
    adsbh_kernel<<<blocks, 256>>>(a, b, zs, out, B);
}

// round 7
// speedup vs baseline: 2.9192x; 2.6397x over previous
#include <cuda_runtime.h>
#include <math.h>

#define NUL 2000
#define NUV 1500
#define EPSF 1e-6f
#define EPS2 1e-12f

// Principal sqrt of w = x+iy -> (sx, sy), plus rq = 1/|w| (rsqrt of |w|^2).
__device__ __forceinline__ void csqrt_rq(float x, float y,
                                         float &sx, float &sy, float &rq)
{
    float q  = fmaf(x, x, y * y);
    rq       = rsqrtf(q);
    float m  = q * rq;                       // |w|
    float tt = fmaf(0.5f, m, 0.5f * fabsf(x));
    float it = rsqrtf(tt);
    float tb = tt * it;                      // sqrt((|w|+|x|)/2)
    if (x >= 0.0f) { sx = tb;                   sy = 0.5f * y * it; }
    else           { sx = 0.5f * fabsf(y) * it; sy = copysignf(tb, y); }
}

// expm1: poly for small |x|, expf-1 otherwise (ex = __expf(x) passed in).
__device__ __forceinline__ float fast_expm1(float x, float ex)
{
    float p = fmaf(x, 8.3333333e-3f, 4.1666667e-2f);
    p = fmaf(p, x, 1.6666667e-1f);
    p = fmaf(p, x, 0.5f);
    p = fmaf(p, x, 1.0f);
    float poly = x * p;
    return (fabsf(x) < 0.2f) ? poly : (ex - 1.0f);
}

__global__ void __launch_bounds__(256)
adsbh_kernel(const float* __restrict__ A,
             const float* __restrict__ Bc,
             const float* __restrict__ ZS,
             float* __restrict__ out, int B)
{
    __shared__ float red[8][4];

    const int w    = threadIdx.x >> 5;
    const int lane = threadIdx.x & 31;
    const int slot = w >> 1;          // 4 zs per block
    const int par  = w & 1;           // 2 warps per zs
    const int zi   = blockIdx.x * 4 + slot;
    const bool valid = (zi < B);

    const float a1 = A[0], a2 = A[1], a3 = A[2], a4 = A[3], a5 = A[4];
    const float b1 = Bc[0], b2 = Bc[1], b3 = Bc[2], b4 = Bc[3], b5 = Bc[4];

    const float zsv = valid ? ZS[zi] : 0.5f;
    const float zs2 = zsv * zsv;
    const float zs3 = zs2 * zsv;
    const float zs4 = zs2 * zs2;
    const float zs5 = zs4 * zsv;

    const float Pazs   = zsv * fmaf(zsv, fmaf(zsv, fmaf(zsv, fmaf(zsv, a5, a4), a3), a2), a1);
    const float e_pazs = expf(Pazs);
    const float fzs    = (1.0f - zs4) * e_pazs;
    const float epz4   = e_pazs * zs4;

    // a_i * zs^i and b_i * zs^i (polys become polys in u)
    const float Az1 = a1 * zsv, Az2 = a2 * zs2, Az3 = a3 * zs3, Az4 = a4 * zs4, Az5 = a5 * zs5;
    const float Bz1 = b1 * zsv, Bz2 = b2 * zs2, Bz3 = b3 * zs3, Bz4 = b4 * zs4, Bz5 = b5 * zs5;

    const float hLf = (float)((1.0 - 2.0e-6) / (double)(NUL - 1));
    const float hVf = (float)((1.0 - 2.0e-6) / (double)(NUV - 1));

    float accLr = 0.0f, accLi = 0.0f, accVr = 0.0f, accVi = 0.0f;

    int   kL  = lane + 32 * par;
    int   kV  = kL;
    float kLf = (float)kL,            kVf = (float)kV;
    float rLf = (float)(NUL - 1 - kL), rVf = (float)(NUV - 1 - kV);

    while (kL < NUL || kV < NUV) {
        // ============================ L point ============================
        if (kL < NUL) {
            const float u   = fmaf(kLf, hLf, EPSF);       // linspace, FP32-exact
            const float omu = fmaf(rLf, hLf, EPSF);       // 1-u without cancellation

            float s2 = u + 1.0f;
            float s3 = fmaf(s2, u, 1.0f);
            float s4 = fmaf(s3, u, 1.0f);
            float s5 = fmaf(s4, u, 1.0f);
            const float sumA = fmaf(Az5, s5, fmaf(Az4, s4, fmaf(Az3, s3, fmaf(Az2, s2, Az1))));
            const float dPa  = -omu * sumA;
            const float ex   = __expf(dPa);
            const float Em   = fast_expm1(dPa, ex);

            const float u2   = u * u;
            const float u4   = u2 * u2;
            const float z4   = zs4 * u4;
            const float omz4 = 1.0f - z4;

            const float oEm   = omz4 * Em;
            const float om_u4 = omu * s4;                 // 1 - u^4, stable
            const float S     = epz4 * (oEm + om_u4);     // zs^4 f(z) - z^4 f(zs)
            const float N     = epz4 * (omz4 + oEm);      // zs^4 f(z)
            const float R     = fmaf(z4, fzs, EPSF);
            const float rden  = __fdividef(1.0f, fmaf(R, R, EPS2));
            const float Dre   = fmaf(fmaf(R, S - EPSF, -EPS2), rden, EPSF);
            const float Dim   = fmaf(-(N * rden), EPSF, EPSF);

            // fold 1/sqrt(omz4) into the complex sqrt: w' = omz4 * D
            const float wr = omz4 * Dre;
            const float wi = omz4 * Dim;
            float sx, sy, rq;
            csqrt_rq(wr, wi, sx, sy, rq);

            const float Pb = u * fmaf(u, fmaf(u, fmaf(u, fmaf(u, Bz5, Bz4), Bz3), Bz2), Bz1);
            const float E  = __expf(0.5f * Pb);
            const float wk = (kL == 0 || kL == NUL - 1) ? 0.5f : 1.0f;
            const float rr = E * rq * wk;                  // E / |w'|
            accLr = fmaf(rr,  sx, accLr);
            accLi = fmaf(rr, -sy, accLi);
        }

        // ============================ V point ============================
        if (kV < NUV) {
            const float u   = fmaf(kVf, hVf, EPSF);
            const float omu = fmaf(rVf, hVf, EPSF);

            float s2 = u + 1.0f;
            float s3 = fmaf(s2, u, 1.0f);
            float s4 = fmaf(s3, u, 1.0f);
            float s5 = fmaf(s4, u, 1.0f);
            const float sumA = fmaf(Az5, s5, fmaf(Az4, s4, fmaf(Az3, s3, fmaf(Az2, s2, Az1))));
            const float dPa  = -omu * sumA;
            const float ex   = __expf(dPa);
            const float Em   = fast_expm1(dPa, ex);

            const float u2   = u * u;
            const float u4   = u2 * u2;
            const float z2   = zs2 * u2;
            const float z4   = zs4 * u4;
            const float omz4 = 1.0f - z4;

            const float oEm   = omz4 * Em;
            const float om_u4 = omu * s4;
            const float S     = epz4 * (oEm + om_u4);
            const float N     = epz4 * (omz4 + oEm);      // zs^4 f(z)
            const float Rp    = N + EPSF;
            const float M     = z4 * fzs;

            const float cr  = z2 + EPSF;
            const float crq = fmaf(cr, cr, EPS2);
            const float rpq = fmaf(Rp, Rp, EPS2);
            const float rb  = __fdividef(1.0f, crq * rpq); // one rcp for both
            const float rden = rb * crq;                   // = 1/rpq
            const float rc2  = rb * rpq;                   // = 1/crq

            const float ire = fmaf(fmaf(Rp, S + EPSF, EPS2), rden, EPSF);
            const float iim = fmaf(M * rden, EPSF, EPSF);

            float sx, sy, rq;
            csqrt_rq(ire, iim, sx, sy, rq);

            const float Pb = u * fmaf(u, fmaf(u, fmaf(u, fmaf(u, Bz5, Bz4), Bz3), Bz2), Bz1);
            const float Ep = __expf(0.5f * (Pazs + dPa + Pb));

            const float t   = Ep * rq;                     // Ep / |inner|
            const float tre = fmaf(t, sx, -1.0f);
            const float tim = -t * sy;

            const float Ire = fmaf(tre, cr,  tim * EPSF) * rc2;
            const float Iim = fmaf(tim, cr, -tre * EPSF) * rc2;

            const float wk = (kV == 0 || kV == NUV - 1) ? 0.5f : 1.0f;
            accVr = fmaf(wk, Ire, accVr);
            accVi = fmaf(wk, Iim, accVi);
        }

        kL += 64; kV += 64;
        kLf += 64.0f; kVf += 64.0f;
        rLf -= 64.0f; rVf -= 64.0f;
    }

    // warp-internal reduction
    #pragma unroll
    for (int o = 16; o > 0; o >>= 1) {
        accLr += __shfl_xor_sync(0xFFFFFFFFu, accLr, o);
        accLi += __shfl_xor_sync(0xFFFFFFFFu, accLi, o);
        accVr += __shfl_xor_sync(0xFFFFFFFFu, accVr, o);
        accVi += __shfl_xor_sync(0xFFFFFFFFu, accVi, o);
    }
    if (lane == 0) {
        red[w][0] = accLr;
        red[w][1] = accLi;
        red[w][2] = accVr;
        red[w][3] = accVi;
    }
    __syncthreads();

    // combine warp pair per zs and write out
    if (threadIdx.x < 4) {
        const int zo = blockIdx.x * 4 + threadIdx.x;
        if (zo < B) {
            const int e = 2 * threadIdx.x;
            const float Lr = red[e][0] + red[e + 1][0];
            const float Li = red[e][1] + red[e + 1][1];
            const float Vr = red[e][2] + red[e + 1][2];
            const float Vi = red[e][3] + red[e + 1][3];

            const float z0 = ZS[zo];
            const float sL = (float)((2.0 / M_PI) * ((1.0 - 2.0e-6) / (double)(NUL - 1))) * z0;
            const float sV = (float)(2.0 * M_PI * ((1.0 - 2.0e-6) / (double)(NUV - 1))) * z0;
            const float vdisc = (float)(2.0 * M_PI) / z0;

            out[0 * B + zo] = Lr * sL;
            out[1 * B + zo] = Li * sL;
            out[2 * B + zo] = Vr * sV - vdisc;
            out[3 * B + zo] = Vi * sV;
        }
    }
}

extern "C" void kernel_launch(void* const* d_in, const int* in_sizes, int n_in,
                              void* d_out, int out_size)
{
    const float* a  = (const float*)d_in[0];
    const float* b  = (const float*)d_in[1];
    const float* zs = (const float*)d_in[2];
    float* out = (float*)d_out;
    const int B = in_sizes[2];

    const int blocks = (B + 3) / 4;   // 4 zs per block (8 warps, 2 per zs)
    adsbh_kernel<<<blocks, 256>>>(a, b, zs, out, B);
}

// round 11
// speedup vs baseline: 2.9755x; 1.0193x over previous
#include <cuda_runtime.h>
#include <math.h>

#define NUL 2000
#define NUV 1500
#define EPSF 1e-6f
#define EPS2 1e-12f
#define NBLK 888   // 148 SMs * 6 blocks

// Principal sqrt of w = x+iy -> (sx, sy), plus rq = 1/|w|.
__device__ __forceinline__ void csqrt_rq(float x, float y,
                                         float &sx, float &sy, float &rq)
{
    float q  = fmaf(x, x, y * y);
    rq       = rsqrtf(q);
    float m  = q * rq;                       // |w|
    float tt = fmaf(0.5f, m, 0.5f * fabsf(x));
    float it = rsqrtf(tt);
    float tb = tt * it;                      // sqrt((|w|+|x|)/2)
    if (x >= 0.0f) { sx = tb;                   sy = 0.5f * y * it; }
    else           { sx = 0.5f * fabsf(y) * it; sy = copysignf(tb, y); }
}

// expm1: poly for small |x|, expf-1 otherwise (ex = __expf(x) passed in).
__device__ __forceinline__ float fast_expm1(float x, float ex)
{
    float p = fmaf(x, 8.3333333e-3f, 4.1666667e-2f);
    p = fmaf(p, x, 1.6666667e-1f);
    p = fmaf(p, x, 0.5f);
    p = fmaf(p, x, 1.0f);
    float poly = x * p;
    return (fabsf(x) < 0.2f) ? poly : (ex - 1.0f);
}

__global__ void __launch_bounds__(256, 6)
adsbh_kernel(const float* __restrict__ A,
             const float* __restrict__ Bc,
             const float* __restrict__ ZS,
             float* __restrict__ out, int B)
{
    __shared__ float red[8][4];

    const int w    = threadIdx.x >> 5;
    const int lane = threadIdx.x & 31;
    const int half = w >> 2;          // which zs of the 2 in this block-round
    const int part = w & 3;           // 4 warps cooperate on one zs

    const float a1 = A[0], a2 = A[1], a3 = A[2], a4 = A[3], a5 = A[4];
    const float b1 = Bc[0], b2 = Bc[1], b3 = Bc[2], b4 = Bc[3], b5 = Bc[4];

    const float hLf = (float)((1.0 - 2.0e-6) / (double)(NUL - 1));
    const float hVf = (float)((1.0 - 2.0e-6) / (double)(NUV - 1));
    const float SLC = (float)((2.0 / M_PI) * ((1.0 - 2.0e-6) / (double)(NUL - 1)));
    const float SVC = (float)(2.0 * M_PI * ((1.0 - 2.0e-6) / (double)(NUV - 1)));
    const float TWO_PI = (float)(2.0 * M_PI);

    for (int base = blockIdx.x * 2; base < B; base += gridDim.x * 2) {
        const int zi = base + half;
        float accLr = 0.0f, accLi = 0.0f, accVr = 0.0f, accVi = 0.0f;

        if (zi < B) {
            const float zsv = ZS[zi];
            const float zs2 = zsv * zsv;
            const float zs3 = zs2 * zsv;
            const float zs4 = zs2 * zs2;
            const float zs5 = zs4 * zsv;

            const float Pazs   = zsv * fmaf(zsv, fmaf(zsv, fmaf(zsv, fmaf(zsv, a5, a4), a3), a2), a1);
            const float hPazs  = 0.5f * Pazs;
            const float e_pazs = expf(Pazs);
            const float fzs    = (1.0f - zs4) * e_pazs;
            const float epz4   = e_pazs * zs4;

            const float Az1 = a1 * zsv, Az2 = a2 * zs2, Az3 = a3 * zs3, Az4 = a4 * zs4, Az5 = a5 * zs5;
            const float Bz1 = b1 * zsv, Bz2 = b2 * zs2, Bz3 = b3 * zs3, Bz4 = b4 * zs4, Bz5 = b5 * zs5;

            // ---- point evaluators (inlined; `edge` is a compile-time literal at call sites) ----
            auto l_point = [&](int k, float kf, bool edge) {
                const float u   = fmaf(kf, hLf, EPSF);
                const float omu = fmaf((float)(NUL - 1) - kf, hLf, EPSF);

                float s2 = u + 1.0f;
                float s3 = fmaf(s2, u, 1.0f);
                float s4 = fmaf(s3, u, 1.0f);
                float s5 = fmaf(s4, u, 1.0f);
                const float sumA = fmaf(Az5, s5, fmaf(Az4, s4, fmaf(Az3, s3, fmaf(Az2, s2, Az1))));
                const float dPa  = -omu * sumA;
                const float ex   = __expf(dPa);
                const float Em   = fast_expm1(dPa, ex);

                const float u2 = u * u, u4 = u2 * u2;
                const float z4 = zs4 * u4;
                const float omz4 = 1.0f - z4;

                const float S  = epz4 * fmaf(omz4, Em, omu * s4);   // zs^4 f(z) - z^4 f(zs), stable
                const float sm = S - EPSF;
                const float R  = fmaf(z4, fzs, EPSF);
                const float q  = fmaf(R, R, EPS2);
                const float rden = __fdividef(1.0f, q);
                const float Rr = R * rden;
                const float e1 = fmaf(-EPS2, rden, EPSF);
                const float Dre = fmaf(sm, Rr, e1);                 // N*R*rden - 1 + eps
                const float nr  = fmaf(sm, rden, Rr);               // N*rden
                const float Dim = fmaf(-EPSF, nr, EPSF);            // eps*(1 - N*rden)

                const float wr = omz4 * Dre;                        // fold 1/sqrt(1-z^4) into sqrt
                const float wi = omz4 * Dim;
                float sx, sy, rq;
                csqrt_rq(wr, wi, sx, sy, rq);

                const float Pb = u * fmaf(u, fmaf(u, fmaf(u, fmaf(u, Bz5, Bz4), Bz3), Bz2), Bz1);
                float rr2 = __expf(0.5f * Pb) * rq;
                if (edge) { if (k == 0 || k == NUL - 1) rr2 *= 0.5f; }
                accLr = fmaf(rr2,  sx, accLr);
                accLi = fmaf(rr2, -sy, accLi);
            };

            auto v_point = [&](int k, float kf, bool edge) {
                const float u   = fmaf(kf, hVf, EPSF);
                const float omu = fmaf((float)(NUV - 1) - kf, hVf, EPSF);

                float s2 = u + 1.0f;
                float s3 = fmaf(s2, u, 1.0f);
                float s4 = fmaf(s3, u, 1.0f);
                float s5 = fmaf(s4, u, 1.0f);
                const float sumA = fmaf(Az5, s5, fmaf(Az4, s4, fmaf(Az3, s3, fmaf(Az2, s2, Az1))));
                const float dPa  = -omu * sumA;
                const float ex   = __expf(dPa);
                const float Em   = fast_expm1(dPa, ex);

                const float u2 = u * u, u4 = u2 * u2;
                const float z2 = zs2 * u2;
                const float z4 = zs4 * u4;
                const float omz4 = 1.0f - z4;

                const float S  = epz4 * fmaf(omz4, Em, omu * s4);
                const float sp = S + EPSF;
                const float M  = z4 * fzs;
                const float Rp = sp + M;                            // zs^4 f(z) + eps
                const float q  = fmaf(Rp, Rp, EPS2);
                const float rden = __fdividef(1.0f, q);
                const float ire = fmaf(fmaf(Rp, sp, EPS2), rden, EPSF);
                const float iim = fmaf(M * rden, EPSF, EPSF);

                float sx, sy, rq;
                csqrt_rq(ire, iim, sx, sy, rq);

                const float Pb = u * fmaf(u, fmaf(u, fmaf(u, fmaf(u, Bz5, Bz4), Bz3), Bz2), Bz1);
                const float Ep = __expf(fmaf(0.5f, dPa + Pb, hPazs));

                const float t   = Ep * rq;
                const float tre = fmaf(t, sx, -1.0f);
                const float tim = -t * sy;

                const float cr  = z2 + EPSF;
                const float crq = fmaf(cr, cr, EPS2);
                const float rc2 = __fdividef(1.0f, crq);
                float Ire = fmaf(tre, cr,  tim * EPSF) * rc2;
                float Iim = fmaf(tim, cr, -tre * EPSF) * rc2;
                if (edge) { if (k == 0 || k == NUV - 1) { Ire *= 0.5f; Iim *= 0.5f; } }
                accVr += Ire;
                accVi += Iim;
            };

            // ---- guard-free phase structure ----
            int   k  = lane + 32 * part;
            float kf = (float)k;

            // phase 1: both integrals, 11 unconditional iterations (k = start .. start+1280)
            l_point(k, kf, true);            // only k==0 can be an edge here
            v_point(k, kf, true);
            k += 128; kf += 128.0f;
            #pragma unroll 2
            for (int i = 1; i < 11; ++i) {
                l_point(k, kf, false);
                v_point(k, kf, false);
                k += 128; kf += 128.0f;
            }
            // phase 2: guarded V tail at k = start + 1408 (covers up to 1503)
            if (k < NUV) v_point(k, kf, true);
            // phase 3: L only, 4 unconditional iterations (k = start+1408 .. start+1792 <= 1919)
            #pragma unroll
            for (int i = 0; i < 4; ++i) {
                l_point(k, kf, false);
                k += 128; kf += 128.0f;
            }
            // phase 4: guarded L tail at k = start + 1920 (covers up to 2047)
            if (k < NUL) l_point(k, kf, true);
        }

        // warp-internal reduction
        #pragma unroll
        for (int o = 16; o > 0; o >>= 1) {
            accLr += __shfl_xor_sync(0xFFFFFFFFu, accLr, o);
            accLi += __shfl_xor_sync(0xFFFFFFFFu, accLi, o);
            accVr += __shfl_xor_sync(0xFFFFFFFFu, accVr, o);
            accVi += __shfl_xor_sync(0xFFFFFFFFu, accVi, o);
        }
        if (lane == 0) {
            red[w][0] = accLr;
            red[w][1] = accLi;
            red[w][2] = accVr;
            red[w][3] = accVi;
        }
        __syncthreads();

        // combine the 4 warps of each zs; 8 threads handle (zs, component)
        if (threadIdx.x < 8) {
            const int t  = threadIdx.x >> 2;
            const int c  = threadIdx.x & 3;
            const int zo = base + t;
            if (zo < B) {
                const int e = 4 * t;
                const float v = red[e][c] + red[e + 1][c] + red[e + 2][c] + red[e + 3][c];
                const float z0 = ZS[zo];
                float r;
                if (c == 2)      r = fmaf(v, SVC * z0, -(TWO_PI / z0));
                else if (c == 3) r = v * (SVC * z0);
                else             r = v * (SLC * z0);
                out[c * B + zo] = r;
            }
        }
        __syncthreads();   // protect red[] before next round
    }
}

extern "C" void kernel_launch(void* const* d_in, const int* in_sizes, int n_in,
                              void* d_out, int out_size)
{
    const float* a  = (const float*)d_in[0];
    const float* b  = (const float*)d_in[1];
    const float* zs = (const float*)d_in[2];
    float* out = (float*)d_out;
    const int B = in_sizes[2];

    int blocks = (B + 1) / 2;
    if (blocks > NBLK) blocks = NBLK;
    adsbh_kernel<<<blocks, 256>>>(a, b, zs, out, B);
}

// round 12
// speedup vs baseline: 3.5286x; 1.1859x over previous
#include <cuda_runtime.h>
#include <math.h>

#define NUL 2000
#define NUV 1500
#define EPSF 1e-6f
#define EPS2 1e-12f
#define L2E 1.4426950408889634f

typedef unsigned long long u64;

__device__ __forceinline__ u64 pk2(float lo, float hi){ u64 r; asm("mov.b64 %0,{%1,%2};" : "=l"(r) : "f"(lo), "f"(hi)); return r; }
__device__ __forceinline__ void upk2(u64 v, float &lo, float &hi){ asm("mov.b64 {%0,%1},%2;" : "=f"(lo), "=f"(hi) : "l"(v)); }
__device__ __forceinline__ u64 bc2(float x){ return pk2(x, x); }
__device__ __forceinline__ u64 f2_(u64 a, u64 b, u64 c){ u64 d; asm("fma.rn.f32x2 %0,%1,%2,%3;" : "=l"(d) : "l"(a), "l"(b), "l"(c)); return d; }
__device__ __forceinline__ u64 m2_(u64 a, u64 b){ u64 d; asm("mul.rn.f32x2 %0,%1,%2;" : "=l"(d) : "l"(a), "l"(b)); return d; }
__device__ __forceinline__ u64 a2_(u64 a, u64 b){ u64 d; asm("add.rn.f32x2 %0,%1,%2;" : "=l"(d) : "l"(a), "l"(b)); return d; }
__device__ __forceinline__ u64 neg2_(u64 a){ u64 d; asm("xor.b64 %0,%1,0x8000000080000000;" : "=l"(d) : "l"(a)); return d; }
__device__ __forceinline__ u64 abs2_(u64 a){ u64 d; asm("and.b64 %0,%1,0x7FFFFFFF7FFFFFFF;" : "=l"(d) : "l"(a)); return d; }

__device__ __forceinline__ float rsq_(float x){ float r; asm("rsqrt.approx.f32 %0,%1;" : "=f"(r) : "f"(x)); return r; }
__device__ __forceinline__ float rcp_(float x){ float r; asm("rcp.approx.f32 %0,%1;" : "=f"(r) : "f"(x)); return r; }
__device__ __forceinline__ float ex2_(float x){ float r; asm("ex2.approx.f32 %0,%1;" : "=f"(r) : "f"(x)); return r; }

__global__ void __launch_bounds__(128)
adsbh_kernel(const float* __restrict__ A,
             const float* __restrict__ Bc,
             const float* __restrict__ ZS,
             float* __restrict__ out, int B)
{
    __shared__ float red[4][4];

    const int w    = threadIdx.x >> 5;
    const int lane = threadIdx.x & 31;
    const int half = w >> 1;              // 2 zs per block
    const int par  = w & 1;               // 2 warps per zs
    const int p    = lane + 32 * par;     // pair index 0..63
    const int zi   = blockIdx.x * 2 + half;
    const bool valid = (zi < B);

    const float a1 = A[0], a2s = A[1], a3 = A[2], a4 = A[3], a5 = A[4];
    const float b1 = Bc[0], b2s = Bc[1], b3 = Bc[2], b4 = Bc[3], b5 = Bc[4];

    const float hLf = (float)((1.0 - 2.0e-6) / (double)(NUL - 1));
    const float hVf = (float)((1.0 - 2.0e-6) / (double)(NUV - 1));

    u64 accLr = 0, accLi = 0, accVr = 0, accVi = 0;

    const float zsv = valid ? ZS[zi] : 0.5f;
    {
        const float zs2 = zsv * zsv;
        const float zs3 = zs2 * zsv;
        const float zs4 = zs2 * zs2;
        const float zs5 = zs4 * zsv;

        const float Pazs   = zsv * fmaf(zsv, fmaf(zsv, fmaf(zsv, fmaf(zsv, a5, a4), a3), a2s), a1);
        const float e_pazs = expf(Pazs);
        const float fzsv   = (1.0f - zs4) * e_pazs;
        const float epz4v  = e_pazs * zs4;

        // packed constants
        const u64 c1    = bc2(1.0f);
        const u64 cn1   = bc2(-1.0f);
        const u64 cHalf = bc2(0.5f);
        const u64 cEPS  = bc2(EPSF);
        const u64 cnEPS = bc2(-EPSF);
        const u64 cE2   = bc2(EPS2);
        const u64 cnE2  = bc2(-EPS2);
        const u64 cL2   = bc2(L2E);
        const u64 cHL2  = bc2(0.5f * L2E);
        const u64 cHPA  = bc2(0.5f * L2E * Pazs);
        const u64 cZS2  = bc2(zs2);
        const u64 cZS4  = bc2(zs4);
        const u64 cEPZ4 = bc2(epz4v);
        const u64 cFZS  = bc2(fzsv);
        const u64 cA1 = bc2(a1 * zsv), cA2 = bc2(a2s * zs2), cA3 = bc2(a3 * zs3);
        const u64 cA4 = bc2(a4 * zs4), cA5 = bc2(a5 * zs5);
        const float FB = 0.5f * L2E;   // exp(0.5*Pb) = ex2(FB*Pb)
        const u64 cB1 = bc2(FB * b1 * zsv), cB2 = bc2(FB * b2s * zs2), cB3 = bc2(FB * b3 * zs3);
        const u64 cB4 = bc2(FB * b4 * zs4), cB5 = bc2(FB * b5 * zs5);
        const u64 cP5 = bc2(8.3333333e-3f), cP4 = bc2(4.1666667e-2f), cP3 = bc2(1.6666667e-1f);
        const u64 cStep  = bc2(128.0f);
        const u64 cStepN = bc2(-128.0f);
        const u64 chL = bc2(hLf), chV = bc2(hVf);

        u64 kf2, rf2;

        // shared front-end: returns Em (packed expm1), dPa, u-chain values via refs
        auto front = [&](u64 h2, u64 &u, u64 &omu, u64 &s4v, u64 &dPa, u64 &Em) {
            u   = f2_(kf2, h2, cEPS);
            omu = f2_(rf2, h2, cEPS);
            u64 s2v = a2_(u, c1);
            u64 s3v = f2_(s2v, u, c1);
            s4v = f2_(s3v, u, c1);
            u64 s5v = f2_(s4v, u, c1);
            u64 sumA = f2_(cA5, s5v, f2_(cA4, s4v, f2_(cA3, s3v, f2_(cA2, s2v, cA1))));
            dPa = neg2_(m2_(omu, sumA));
            u64 dl2 = m2_(dPa, cL2);
            float d2lo, d2hi; upk2(dl2, d2lo, d2hi);
            float exlo = ex2_(d2lo), exhi = ex2_(d2hi);
            u64 pp = f2_(dPa, cP5, cP4);
            pp = f2_(pp, dPa, cP3);
            pp = f2_(pp, dPa, cHalf);
            pp = f2_(pp, dPa, c1);
            u64 poly = m2_(dPa, pp);
            float pl, ph; upk2(poly, pl, ph);
            float emlo = (fabsf(d2lo) < 0.28853901f) ? pl : exlo - 1.0f;
            float emhi = (fabsf(d2hi) < 0.28853901f) ? ph : exhi - 1.0f;
            Em = pk2(emlo, emhi);
        };

        // csqrt of packed (wr, wi): sx,sy packed + rq (1/|w|) packed
        auto csq = [&](u64 wr, u64 wi, u64 &sx2, u64 &sy2, u64 &rq2) {
            u64 qq = f2_(wr, wr, m2_(wi, wi));
            float qqlo, qqhi; upk2(qq, qqlo, qqhi);
            float rqlo = rsq_(qqlo), rqhi = rsq_(qqhi);
            rq2 = pk2(rqlo, rqhi);
            u64 mm = m2_(qq, rq2);
            u64 tt = m2_(cHalf, a2_(mm, abs2_(wr)));
            float ttlo, tthi; upk2(tt, ttlo, tthi);
            float itlo = rsq_(ttlo), ithi = rsq_(tthi);
            float tblo = ttlo * itlo, tbhi = tthi * ithi;
            float wrlo, wrhi, wilo, wihi;
            upk2(wr, wrlo, wrhi); upk2(wi, wilo, wihi);
            float sxlo, sylo, sxhi, syhi;
            if (wrlo >= 0.0f) { sxlo = tblo;                    sylo = 0.5f * wilo * itlo; }
            else              { sxlo = 0.5f * fabsf(wilo) * itlo; sylo = copysignf(tblo, wilo); }
            if (wrhi >= 0.0f) { sxhi = tbhi;                    syhi = 0.5f * wihi * ithi; }
            else              { sxhi = 0.5f * fabsf(wihi) * ithi; syhi = copysignf(tbhi, wihi); }
            sx2 = pk2(sxlo, sxhi);
            sy2 = pk2(sylo, syhi);
        };

        // ---------------- L integral: pairs (k, k+1), k = 2p + 128*i ----------------
        kf2 = pk2((float)(2 * p), (float)(2 * p + 1));
        rf2 = pk2((float)(NUL - 1 - 2 * p), (float)(NUL - 2 - 2 * p));

        auto Lpt = [&](int mode) {
            u64 u, omu, s4v, dPa, Em;
            front(chL, u, omu, s4v, dPa, Em);

            u64 u2v = m2_(u, u);
            u64 u4v = m2_(u2v, u2v);
            u64 z4  = m2_(cZS4, u4v);
            u64 omz4 = f2_(z4, cn1, c1);

            u64 S  = m2_(cEPZ4, f2_(omz4, Em, m2_(omu, s4v)));
            u64 sm = a2_(S, cnEPS);
            u64 R  = f2_(z4, cFZS, cEPS);
            u64 q  = f2_(R, R, cE2);
            // numerator of D = n/q:  n_re = sm*R + (eps*q - eps^2),  n_im = eps*(q - N)
            u64 nre = f2_(sm, R, f2_(cEPS, q, cnE2));
            u64 Nv  = a2_(sm, R);
            u64 nim = m2_(cEPS, f2_(Nv, cn1, q));
            u64 wr = m2_(omz4, nre);
            u64 wi = m2_(omz4, nim);

            u64 sx2, sy2, rq2;
            csq(wr, wi, sx2, sy2, rq2);

            u64 Pb2 = m2_(u, f2_(u, f2_(u, f2_(u, f2_(u, cB5, cB4), cB3), cB2), cB1));
            float pblo, pbhi; upk2(Pb2, pblo, pbhi);
            float qlo, qhi; upk2(q, qlo, qhi);
            u64 E2  = pk2(ex2_(pblo), ex2_(pbhi));
            u64 qs2 = m2_(q, pk2(rsq_(qlo), rsq_(qhi)));   // sqrt(q)
            u64 rr2 = m2_(m2_(E2, qs2), rq2);              // E*sqrt(q)/|w|

            if (mode == 0) {
                if (p == 0) { float lo, hi; upk2(rr2, lo, hi); rr2 = pk2(0.5f * lo, hi); }
            } else if (mode == 2) {
                float lo, hi; upk2(rr2, lo, hi);
                if (p >= 40) { lo = 0.0f; hi = 0.0f; }
                else if (p == 39) hi *= 0.5f;
                rr2 = pk2(lo, hi);
            }
            accLr = f2_(rr2, sx2, accLr);
            accLi = f2_(neg2_(rr2), sy2, accLi);
            kf2 = a2_(kf2, cStep);
            rf2 = a2_(rf2, cStepN);
        };

        Lpt(0);
        #pragma unroll 2
        for (int i = 1; i < 15; ++i) Lpt(1);
        Lpt(2);

        // ---------------- V integral: pairs (k, k+1), k = 2p + 128*i ----------------
        kf2 = pk2((float)(2 * p), (float)(2 * p + 1));
        rf2 = pk2((float)(NUV - 1 - 2 * p), (float)(NUV - 2 - 2 * p));

        auto Vpt = [&](int mode) {
            u64 u, omu, s4v, dPa, Em;
            front(chV, u, omu, s4v, dPa, Em);

            u64 u2v = m2_(u, u);
            u64 u4v = m2_(u2v, u2v);
            u64 z2  = m2_(cZS2, u2v);
            u64 z4  = m2_(cZS4, u4v);
            u64 omz4 = f2_(z4, cn1, c1);

            u64 S  = m2_(cEPZ4, f2_(omz4, Em, m2_(omu, s4v)));
            u64 sp = a2_(S, cEPS);
            u64 M  = m2_(z4, cFZS);
            u64 Rp = a2_(sp, M);
            u64 q  = f2_(Rp, Rp, cE2);
            // numerator of inner = n/q: n_re = Rp*sp + eps^2 + eps*q, n_im = eps*(q + M)
            u64 nre = f2_(Rp, sp, f2_(cEPS, q, cE2));
            u64 nim = m2_(cEPS, a2_(q, M));

            u64 sx2, sy2, rq2;
            csq(nre, nim, sx2, sy2, rq2);

            u64 Pb2 = m2_(u, f2_(u, f2_(u, f2_(u, f2_(u, cB5, cB4), cB3), cB2), cB1));
            u64 arg2 = f2_(dPa, cHL2, a2_(Pb2, cHPA));     // log2(Ep)
            float aglo, aghi; upk2(arg2, aglo, aghi);
            float qlo, qhi; upk2(q, qlo, qhi);
            u64 Ep2 = pk2(ex2_(aglo), ex2_(aghi));
            u64 qs2 = m2_(q, pk2(rsq_(qlo), rsq_(qhi)));
            u64 t2  = m2_(m2_(Ep2, qs2), rq2);             // Ep*sqrt(q)/|n|

            u64 tre2 = f2_(t2, sx2, cn1);
            u64 tim2 = neg2_(m2_(t2, sy2));

            u64 cr2  = a2_(z2, cEPS);
            u64 crq2 = f2_(cr2, cr2, cE2);
            float cqlo, cqhi; upk2(crq2, cqlo, cqhi);
            u64 rc2 = pk2(rcp_(cqlo), rcp_(cqhi));
            u64 Ire2 = m2_(f2_(tre2, cr2, m2_(tim2, cEPS)), rc2);
            u64 Iim2 = m2_(f2_(tim2, cr2, neg2_(m2_(tre2, cEPS))), rc2);

            if (mode == 0) {
                u64 w2 = pk2((p == 0) ? 0.5f : 1.0f, 1.0f);
                accVr = f2_(w2, Ire2, accVr);
                accVi = f2_(w2, Iim2, accVi);
            } else if (mode == 2) {
                float wl = (p >= 46) ? 0.0f : 1.0f;
                float wh = (p >= 46) ? 0.0f : ((p == 45) ? 0.5f : 1.0f);
                u64 w2 = pk2(wl, wh);
                accVr = f2_(w2, Ire2, accVr);
                accVi = f2_(w2, Iim2, accVi);
            } else {
                accVr = a2_(accVr, Ire2);
                accVi = a2_(accVi, Iim2);
            }
            kf2 = a2_(kf2, cStep);
            rf2 = a2_(rf2, cStepN);
        };

        Vpt(0);
        #pragma unroll 2
        for (int i = 1; i < 11; ++i) Vpt(1);
        Vpt(2);
    }

    // sum packed halves
    float lr0, lr1, li0, li1, vr0, vr1, vi0, vi1;
    upk2(accLr, lr0, lr1); upk2(accLi, li0, li1);
    upk2(accVr, vr0, vr1); upk2(accVi, vi0, vi1);
    float aLr = lr0 + lr1, aLi = li0 + li1, aVr = vr0 + vr1, aVi = vi0 + vi1;

    #pragma unroll
    for (int o = 16; o > 0; o >>= 1) {
        aLr += __shfl_xor_sync(0xFFFFFFFFu, aLr, o);
        aLi += __shfl_xor_sync(0xFFFFFFFFu, aLi, o);
        aVr += __shfl_xor_sync(0xFFFFFFFFu, aVr, o);
        aVi += __shfl_xor_sync(0xFFFFFFFFu, aVi, o);
    }
    if (lane == 0) {
        red[w][0] = aLr;
        red[w][1] = aLi;
        red[w][2] = aVr;
        red[w][3] = aVi;
    }
    __syncthreads();

    if (threadIdx.x < 8) {
        const int t  = threadIdx.x >> 2;
        const int c  = threadIdx.x & 3;
        const int zo = blockIdx.x * 2 + t;
        if (zo < B) {
            const int e = 2 * t;
            const float v = red[e][c] + red[e + 1][c];
            const float z0 = ZS[zo];
            const float SLC = (float)((2.0 / M_PI) * ((1.0 - 2.0e-6) / (double)(NUL - 1)));
            const float SVC = (float)(2.0 * M_PI * ((1.0 - 2.0e-6) / (double)(NUV - 1)));
            const float TWO_PI = (float)(2.0 * M_PI);
            float r;
            if (c == 2)      r = fmaf(v, SVC * z0, -(TWO_PI / z0));
            else if (c == 3) r = v * (SVC * z0);
            else             r = v * (SLC * z0);
            out[c * B + zo] = r;
        }
    }
}

extern "C" void kernel_launch(void* const* d_in, const int* in_sizes, int n_in,
                              void* d_out, int out_size)
{
    const float* a  = (const float*)d_in[0];
    const float* b  = (const float*)d_in[1];
    const float* zs = (const float*)d_in[2];
    float* out = (float*)d_out;
    const int B = in_sizes[2];

    const int blocks = (B + 1) / 2;   // 2 zs per block, 128 threads
    adsbh_kernel<<<blocks, 128>>>(a, b, zs, out, B);
}

// round 13
// speedup vs baseline: 3.5460x; 1.0049x over previous
#include <cuda_runtime.h>
#include <math.h>

#define NUL 2000
#define NUV 1500
#define EPSF 1e-6f
#define EPS2 1e-12f
#define L2E 1.4426950408889634f

typedef unsigned long long u64;

__device__ __forceinline__ u64 pk2(float lo, float hi){ u64 r; asm("mov.b64 %0,{%1,%2};" : "=l"(r) : "f"(lo), "f"(hi)); return r; }
__device__ __forceinline__ void upk2(u64 v, float &lo, float &hi){ asm("mov.b64 {%0,%1},%2;" : "=f"(lo), "=f"(hi) : "l"(v)); }
__device__ __forceinline__ u64 bc2(float x){ return pk2(x, x); }
__device__ __forceinline__ u64 f2_(u64 a, u64 b, u64 c){ u64 d; asm("fma.rn.f32x2 %0,%1,%2,%3;" : "=l"(d) : "l"(a), "l"(b), "l"(c)); return d; }
__device__ __forceinline__ u64 m2_(u64 a, u64 b){ u64 d; asm("mul.rn.f32x2 %0,%1,%2;" : "=l"(d) : "l"(a), "l"(b)); return d; }
__device__ __forceinline__ u64 a2_(u64 a, u64 b){ u64 d; asm("add.rn.f32x2 %0,%1,%2;" : "=l"(d) : "l"(a), "l"(b)); return d; }
__device__ __forceinline__ u64 abs2_(u64 a){ u64 d; asm("and.b64 %0,%1,0x7FFFFFFF7FFFFFFF;" : "=l"(d) : "l"(a)); return d; }

__device__ __forceinline__ float rsq_(float x){ float r; asm("rsqrt.approx.f32 %0,%1;" : "=f"(r) : "f"(x)); return r; }
__device__ __forceinline__ float rcp_(float x){ float r; asm("rcp.approx.f32 %0,%1;" : "=f"(r) : "f"(x)); return r; }
__device__ __forceinline__ float ex2_(float x){ float r; asm("ex2.approx.f32 %0,%1;" : "=f"(r) : "f"(x)); return r; }

__global__ void __launch_bounds__(128, 8)
adsbh_kernel(const float* __restrict__ A,
             const float* __restrict__ Bc,
             const float* __restrict__ ZS,
             float* __restrict__ out, int B)
{
    __shared__ float red[4][4];

    const int w    = threadIdx.x >> 5;
    const int lane = threadIdx.x & 31;
    const int p    = lane + 32 * w;       // pair index 0..127 (4 warps, 1 zs)
    const int zi   = blockIdx.x;

    const float a1 = A[0], a2s = A[1], a3 = A[2], a4 = A[3], a5 = A[4];
    const float b1 = Bc[0], b2s = Bc[1], b3 = Bc[2], b4 = Bc[3], b5 = Bc[4];

    const float hLf = (float)((1.0 - 2.0e-6) / (double)(NUL - 1));
    const float hVf = (float)((1.0 - 2.0e-6) / (double)(NUV - 1));

    const float zsv = ZS[zi];
    const float zs2 = zsv * zsv;
    const float zs3 = zs2 * zsv;
    const float zs4 = zs2 * zs2;
    const float zs5 = zs4 * zsv;

    const float Pazs   = zsv * fmaf(zsv, fmaf(zsv, fmaf(zsv, fmaf(zsv, a5, a4), a3), a2s), a1);
    const float e_pazs = expf(Pazs);
    const float fzsv   = (1.0f - zs4) * e_pazs;
    const float epz4v  = e_pazs * zs4;

    // packed constants (all negations folded into constants)
    const u64 c1    = bc2(1.0f);
    const u64 cn1   = bc2(-1.0f);
    const u64 cHalf = bc2(0.5f);
    const u64 cEPS  = bc2(EPSF);
    const u64 cnEPS = bc2(-EPSF);
    const u64 cE2   = bc2(EPS2);
    const u64 cnE2  = bc2(-EPS2);
    const u64 cnL2  = bc2(-L2E);
    const u64 cnHL2 = bc2(-0.5f * L2E);
    const u64 cHPA  = bc2(0.5f * L2E * Pazs);
    const u64 cZS2  = bc2(zs2);
    const u64 cZS4  = bc2(zs4);
    const u64 cEPZ4 = bc2(epz4v);
    const u64 cFZS  = bc2(fzsv);
    const u64 cA1 = bc2(a1 * zsv), cA2 = bc2(a2s * zs2), cA3 = bc2(a3 * zs3);
    const u64 cA4 = bc2(a4 * zs4), cA5 = bc2(a5 * zs5);
    const float FB = 0.5f * L2E;   // exp(0.5*Pb) = ex2(FB*Pb)
    const u64 cB1 = bc2(FB * b1 * zsv), cB2 = bc2(FB * b2s * zs2), cB3 = bc2(FB * b3 * zs3);
    const u64 cB4 = bc2(FB * b4 * zs4), cB5 = bc2(FB * b5 * zs5);
    // Horner for 1 - e^{-y} = y*(1 - y/2 + y^2/6 - y^3/24 + y^4/120)
    const u64 cQ5 = bc2(8.3333333e-3f), cQ4 = bc2(-4.1666667e-2f);
    const u64 cQ3 = bc2(1.6666667e-1f), cQ2 = bc2(-0.5f);
    const u64 cStep  = bc2(256.0f);
    const u64 cStepN = bc2(-256.0f);
    const u64 chL = bc2(hLf), chV = bc2(hVf);

    u64 accLr = 0, accLiP = 0, accVr = 0, accViN = 0;

    u64 kL2 = pk2((float)(2 * p), (float)(2 * p + 1));
    u64 rL2 = pk2((float)(NUL - 1 - 2 * p), (float)(NUL - 2 - 2 * p));
    u64 kV2 = kL2;
    u64 rV2 = pk2((float)(NUV - 1 - 2 * p), (float)(NUV - 2 - 2 * p));

    // shared front-end: u, omu, s4 chain, y = -dPa, Emn = 1 - e^{dPa}
    auto front = [&](u64 kf2, u64 rf2, u64 h2, u64 &u, u64 &omu, u64 &s4v, u64 &y, u64 &Emn) {
        u   = f2_(kf2, h2, cEPS);
        omu = f2_(rf2, h2, cEPS);
        u64 s2v = a2_(u, c1);
        u64 s3v = f2_(s2v, u, c1);
        s4v = f2_(s3v, u, c1);
        u64 s5v = f2_(s4v, u, c1);
        u64 sumA = f2_(cA5, s5v, f2_(cA4, s4v, f2_(cA3, s3v, f2_(cA2, s2v, cA1))));
        y = m2_(omu, sumA);                 // = -dPa (stable near u->1)
        u64 arg = m2_(y, cnL2);             // L2E * dPa
        float alo, ahi; upk2(arg, alo, ahi);
        float exlo = ex2_(alo), exhi = ex2_(ahi);
        u64 h = f2_(y, cQ5, cQ4);
        h = f2_(h, y, cQ3);
        h = f2_(h, y, cQ2);
        h = f2_(h, y, c1);
        u64 ps = m2_(y, h);                 // 1 - e^{-y}, small-|y| path
        float pl, ph; upk2(ps, pl, ph);
        float el = (fabsf(alo) < 0.28853901f) ? pl : (1.0f - exlo);
        float eh = (fabsf(ahi) < 0.28853901f) ? ph : (1.0f - exhi);
        Emn = pk2(el, eh);
    };

    // packed principal csqrt of (wr, wi) -> sx2, sy2, rq2 = 1/|w|
    auto csq = [&](u64 wr, u64 wi, u64 &sx2, u64 &sy2, u64 &rq2) {
        u64 qq = f2_(wr, wr, m2_(wi, wi));
        float qqlo, qqhi; upk2(qq, qqlo, qqhi);
        rq2 = pk2(rsq_(qqlo), rsq_(qqhi));
        u64 mm = m2_(qq, rq2);                       // |w|
        u64 tt = m2_(cHalf, a2_(mm, abs2_(wr)));     // (|w|+|x|)/2
        float ttlo, tthi; upk2(tt, ttlo, tthi);
        u64 itp = pk2(rsq_(ttlo), rsq_(tthi));
        u64 tb2 = m2_(tt, itp);                      // sqrt((|w|+|x|)/2)
        u64 hy2 = m2_(m2_(wi, itp), cHalf);          // y/(2t)
        float wrlo, wrhi, tblo, tbhi, hylo, hyhi;
        upk2(wr, wrlo, wrhi); upk2(tb2, tblo, tbhi); upk2(hy2, hylo, hyhi);
        float sxlo, sylo, sxhi, syhi;
        if (wrlo >= 0.0f) { sxlo = tblo;         sylo = hylo; }
        else              { sxlo = fabsf(hylo);  sylo = copysignf(tblo, hylo); }
        if (wrhi >= 0.0f) { sxhi = tbhi;         syhi = hyhi; }
        else              { sxhi = fabsf(hyhi);  syhi = copysignf(tbhi, hyhi); }
        sx2 = pk2(sxlo, sxhi);
        sy2 = pk2(sylo, syhi);
    };

    // ---------------- L point pair ----------------
    auto Lpt = [&](int mode) {
        u64 u, omu, s4v, y, Emn;
        front(kL2, rL2, chL, u, omu, s4v, y, Emn);

        u64 u2v = m2_(u, u);
        u64 u4v = m2_(u2v, u2v);
        u64 z4  = m2_(cZS4, u4v);
        u64 omz4  = f2_(z4, cn1, c1);
        u64 omz4n = a2_(z4, cn1);

        u64 S  = m2_(cEPZ4, f2_(omz4n, Emn, m2_(omu, s4v)));  // zs^4 f(z) - z^4 f(zs)
        u64 sm = a2_(S, cnEPS);
        u64 R  = f2_(z4, cFZS, cEPS);
        u64 q  = f2_(R, R, cE2);
        u64 nre = f2_(sm, R, f2_(cEPS, q, cnE2));
        u64 Nv  = a2_(sm, R);
        u64 nim = m2_(cEPS, f2_(Nv, cn1, q));
        u64 wr = m2_(omz4, nre);
        u64 wi = m2_(omz4, nim);

        u64 sx2, sy2, rq2;
        csq(wr, wi, sx2, sy2, rq2);

        u64 Pb2 = m2_(u, f2_(u, f2_(u, f2_(u, f2_(u, cB5, cB4), cB3), cB2), cB1));
        float pblo, pbhi; upk2(Pb2, pblo, pbhi);
        float qlo, qhi; upk2(q, qlo, qhi);
        u64 E2  = pk2(ex2_(pblo), ex2_(pbhi));
        u64 qs2 = m2_(q, pk2(rsq_(qlo), rsq_(qhi)));  // sqrt(q)
        u64 rr2 = m2_(m2_(E2, qs2), rq2);

        if (mode == 0) {
            rr2 = m2_(rr2, pk2((p == 0) ? 0.5f : 1.0f, 1.0f));
        } else if (mode == 2) {
            float wl = (p <= 103) ? 1.0f : 0.0f;
            float wh = (p < 103) ? 1.0f : ((p == 103) ? 0.5f : 0.0f);
            rr2 = m2_(rr2, pk2(wl, wh));
        }
        accLr  = f2_(rr2, sx2, accLr);
        accLiP = f2_(rr2, sy2, accLiP);     // negated at writeout
        kL2 = a2_(kL2, cStep);
        rL2 = a2_(rL2, cStepN);
    };

    // ---------------- V point pair ----------------
    auto Vpt = [&](int mode) {
        u64 u, omu, s4v, y, Emn;
        front(kV2, rV2, chV, u, omu, s4v, y, Emn);

        u64 u2v = m2_(u, u);
        u64 u4v = m2_(u2v, u2v);
        u64 z2  = m2_(cZS2, u2v);
        u64 z4  = m2_(cZS4, u4v);
        u64 omz4n = a2_(z4, cn1);

        u64 S  = m2_(cEPZ4, f2_(omz4n, Emn, m2_(omu, s4v)));
        u64 sp = a2_(S, cEPS);
        u64 M  = m2_(z4, cFZS);
        u64 Rp = a2_(sp, M);
        u64 q  = f2_(Rp, Rp, cE2);
        u64 nre = f2_(Rp, sp, f2_(cEPS, q, cE2));
        u64 nim = m2_(cEPS, a2_(q, M));

        u64 sx2, sy2, rq2;
        csq(nre, nim, sx2, sy2, rq2);

        u64 Pb2  = m2_(u, f2_(u, f2_(u, f2_(u, f2_(u, cB5, cB4), cB3), cB2), cB1));
        u64 arg2 = f2_(y, cnHL2, a2_(Pb2, cHPA));    // log2(Ep)
        float aglo, aghi; upk2(arg2, aglo, aghi);
        float qlo, qhi; upk2(q, qlo, qhi);
        u64 Ep2 = pk2(ex2_(aglo), ex2_(aghi));
        u64 qs2 = m2_(q, pk2(rsq_(qlo), rsq_(qhi)));
        u64 t2  = m2_(m2_(Ep2, qs2), rq2);

        u64 tre2 = f2_(t2, sx2, cn1);
        u64 tp2  = m2_(t2, sy2);                     // = -tim

        u64 cr2  = a2_(z2, cEPS);
        u64 crq2 = f2_(cr2, cr2, cE2);
        float cqlo, cqhi; upk2(crq2, cqlo, cqhi);
        u64 rc2 = pk2(rcp_(cqlo), rcp_(cqhi));
        u64 Ire2  = m2_(f2_(tre2, cr2, m2_(tp2, cnEPS)), rc2);
        u64 IimN2 = m2_(f2_(tp2, cr2, m2_(tre2, cEPS)), rc2);  // = -Iim

        if (mode == 0) {
            u64 w2 = pk2((p == 0) ? 0.5f : 1.0f, 1.0f);
            accVr  = f2_(w2, Ire2,  accVr);
            accViN = f2_(w2, IimN2, accViN);
        } else if (mode == 2) {
            float wl = (p <= 109) ? 1.0f : 0.0f;
            float wh = (p < 109) ? 1.0f : ((p == 109) ? 0.5f : 0.0f);
            u64 w2 = pk2(wl, wh);
            accVr  = f2_(w2, Ire2,  accVr);
            accViN = f2_(w2, IimN2, accViN);
        } else {
            accVr  = a2_(accVr,  Ire2);
            accViN = a2_(accViN, IimN2);
        }
        kV2 = a2_(kV2, cStep);
        rV2 = a2_(rV2, cStepN);
    };

    // ---- merged schedule: L has 8 pair-iterations, V has 6; interleave for ILP ----
    Lpt(0); Vpt(0);                       // i = 0 (edges at k=0)
    #pragma unroll
    for (int i = 1; i < 5; ++i) {         // i = 1..4
        Lpt(1); Vpt(1);
    }
    Lpt(1); Vpt(2);                       // i = 5 (V tail)
    Lpt(1);                               // i = 6
    Lpt(2);                               // i = 7 (L tail)

    // sum packed halves
    float lr0, lr1, li0, li1, vr0, vr1, vi0, vi1;
    upk2(accLr, lr0, lr1); upk2(accLiP, li0, li1);
    upk2(accVr, vr0, vr1); upk2(accViN, vi0, vi1);
    float aLr = lr0 + lr1, aLi = li0 + li1, aVr = vr0 + vr1, aVi = vi0 + vi1;

    #pragma unroll
    for (int o = 16; o > 0; o >>= 1) {
        aLr += __shfl_xor_sync(0xFFFFFFFFu, aLr, o);
        aLi += __shfl_xor_sync(0xFFFFFFFFu, aLi, o);
        aVr += __shfl_xor_sync(0xFFFFFFFFu, aVr, o);
        aVi += __shfl_xor_sync(0xFFFFFFFFu, aVi, o);
    }
    if (lane == 0) {
        red[w][0] = aLr;
        red[w][1] = -aLi;     // undo positive-imag accumulation
        red[w][2] = aVr;
        red[w][3] = -aVi;
    }
    __syncthreads();

    if (threadIdx.x < 4) {
        const int c = threadIdx.x;
        const float v = red[0][c] + red[1][c] + red[2][c] + red[3][c];
        const float SLC = (float)((2.0 / M_PI) * ((1.0 - 2.0e-6) / (double)(NUL - 1)));
        const float SVC = (float)(2.0 * M_PI * ((1.0 - 2.0e-6) / (double)(NUV - 1)));
        const float TWO_PI = (float)(2.0 * M_PI);
        float r;
        if (c == 2)      r = fmaf(v, SVC * zsv, -(TWO_PI / zsv));
        else if (c == 3) r = v * (SVC * zsv);
        else             r = v * (SLC * zsv);
        out[c * B + zi] = r;
    }
}

extern "C" void kernel_launch(void* const* d_in, const int* in_sizes, int n_in,
                              void* d_out, int out_size)
{
    const float* a  = (const float*)d_in[0];
    const float* b  = (const float*)d_in[1];
    const float* zs = (const float*)d_in[2];
    float* out = (float*)d_out;
    const int B = in_sizes[2];

    adsbh_kernel<<<B, 128>>>(a, b, zs, out, B);   // 1 zs per 128-thread block
}

// round 15
// speedup vs baseline: 4.7750x; 1.3466x over previous
#include <cuda_runtime.h>
#include <math.h>

#define NUL 2000
#define NUV 1500
#define EPSF 1e-6f
#define EPS2 1e-12f
#define L2E 1.4426950408889634f

// Composite quadrature layout (verified: weight sums == N-1 exactly)
#define K0L   1920      // L coarse/tail boundary (16 + 4*476)
#define SMEL  968       // (K0L+16)/2 : last middle slot for L
#define NSL   1048      // total L slots
#define K0V   1456      // V boundary (16 + 4*360)
#define SMEV  736       // (K0V+16)/2
#define NSV   780       // total V slots
#define DELTA 0.03f     // |D_re| flag threshold

typedef unsigned long long u64;

__device__ __forceinline__ u64 pk2(float lo, float hi){ u64 r; asm("mov.b64 %0,{%1,%2};" : "=l"(r) : "f"(lo), "f"(hi)); return r; }
__device__ __forceinline__ void upk2(u64 v, float &lo, float &hi){ asm("mov.b64 {%0,%1},%2;" : "=f"(lo), "=f"(hi) : "l"(v)); }
__device__ __forceinline__ u64 bc2(float x){ return pk2(x, x); }
__device__ __forceinline__ u64 f2_(u64 a, u64 b, u64 c){ u64 d; asm("fma.rn.f32x2 %0,%1,%2,%3;" : "=l"(d) : "l"(a), "l"(b), "l"(c)); return d; }
__device__ __forceinline__ u64 m2_(u64 a, u64 b){ u64 d; asm("mul.rn.f32x2 %0,%1,%2;" : "=l"(d) : "l"(a), "l"(b)); return d; }
__device__ __forceinline__ u64 a2_(u64 a, u64 b){ u64 d; asm("add.rn.f32x2 %0,%1,%2;" : "=l"(d) : "l"(a), "l"(b)); return d; }
__device__ __forceinline__ u64 abs2_(u64 a){ u64 d; asm("and.b64 %0,%1,0x7FFFFFFF7FFFFFFF;" : "=l"(d) : "l"(a)); return d; }

__device__ __forceinline__ float rsq_(float x){ float r; asm("rsqrt.approx.f32 %0,%1;" : "=f"(r) : "f"(x)); return r; }
__device__ __forceinline__ float rcp_(float x){ float r; asm("rcp.approx.f32 %0,%1;" : "=f"(r) : "f"(x)); return r; }
__device__ __forceinline__ float ex2_(float x){ float r; asm("ex2.approx.f32 %0,%1;" : "=f"(r) : "f"(x)); return r; }

// slot -> (k, weight) maps for the composite scheme
__device__ __forceinline__ void mapL(int s, int &k, float &w) {
    if (s < 16)        { k = s;        w = (s == 0) ? 0.5f : 1.0f; }
    else if (s <= SMEL){ k = 2*s - 16; w = (s == 16 || s == SMEL) ? 1.25f : ((k & 2) ? 2.5f : 1.5f); }
    else if (s < NSL)  { k = s + (K0L + 1 - (SMEL + 1)); w = (k == NUL - 1) ? 0.5f : 1.0f; }
    else               { k = 100;      w = 0.0f; }
}
__device__ __forceinline__ void mapV(int s, int &k, float &w) {
    if (s < 16)        { k = s;        w = (s == 0) ? 0.5f : 1.0f; }
    else if (s <= SMEV){ k = 2*s - 16; w = (s == 16 || s == SMEV) ? 1.25f : ((k & 2) ? 2.5f : 1.5f); }
    else if (s < NSV)  { k = s + (K0V + 1 - (SMEV + 1)); w = (k == NUV - 1) ? 0.5f : 1.0f; }
    else               { k = 100;      w = 0.0f; }
}
// plain fine trapezoid maps (fallback path)
__device__ __forceinline__ void mapFL(int s, int &k, float &w) {
    k = (s < NUL) ? s : (NUL - 1);
    w = (s >= NUL) ? 0.0f : ((s == 0 || s == NUL - 1) ? 0.5f : 1.0f);
}
__device__ __forceinline__ void mapFV(int s, int &k, float &w) {
    k = (s < NUV) ? s : (NUV - 1);
    w = (s >= NUV) ? 0.0f : ((s == 0 || s == NUV - 1) ? 0.5f : 1.0f);
}

__global__ void __launch_bounds__(128, 7)
adsbh_kernel(const float* __restrict__ A,
             const float* __restrict__ Bc,
             const float* __restrict__ ZS,
             float* __restrict__ out, int B)
{
    __shared__ float red[4][4];
    __shared__ int sflag;

    const int w    = threadIdx.x >> 5;
    const int lane = threadIdx.x & 31;
    const int p    = lane + 32 * w;       // pair index 0..127
    const int zi   = blockIdx.x;

    if (threadIdx.x == 0) sflag = 0;
    __syncthreads();

    const float a1 = A[0], a2s = A[1], a3 = A[2], a4 = A[3], a5 = A[4];
    const float b1 = Bc[0], b2s = Bc[1], b3 = Bc[2], b4 = Bc[3], b5 = Bc[4];

    const float hLf = (float)((1.0 - 2.0e-6) / (double)(NUL - 1));
    const float hVf = (float)((1.0 - 2.0e-6) / (double)(NUV - 1));

    const float zsv = ZS[zi];
    const float zs2 = zsv * zsv;
    const float zs3 = zs2 * zsv;
    const float zs4 = zs2 * zs2;
    const float zs5 = zs4 * zsv;

    const float Pazs   = zsv * fmaf(zsv, fmaf(zsv, fmaf(zsv, fmaf(zsv, a5, a4), a3), a2s), a1);
    const float e_pazs = expf(Pazs);
    const float fzsv   = (1.0f - zs4) * e_pazs;
    const float epz4v  = e_pazs * zs4;

    const u64 c1    = bc2(1.0f);
    const u64 cn1   = bc2(-1.0f);
    const u64 cHalf = bc2(0.5f);
    const u64 cEPS  = bc2(EPSF);
    const u64 cnEPS = bc2(-EPSF);
    const u64 cE2   = bc2(EPS2);
    const u64 cnE2  = bc2(-EPS2);
    const u64 cnL2  = bc2(-L2E);
    const u64 cnHL2 = bc2(-0.5f * L2E);
    const u64 cHPA  = bc2(0.5f * L2E * Pazs);
    const u64 cZS2  = bc2(zs2);
    const u64 cZS4  = bc2(zs4);
    const u64 cEPZ4 = bc2(epz4v);
    const u64 cFZS  = bc2(fzsv);
    const u64 cA1 = bc2(a1 * zsv), cA2 = bc2(a2s * zs2), cA3 = bc2(a3 * zs3);
    const u64 cA4 = bc2(a4 * zs4), cA5 = bc2(a5 * zs5);
    const float FB = 0.5f * L2E;   // exp(0.5*Pb) = ex2(FB*Pb)
    const u64 cB1 = bc2(FB * b1 * zsv), cB2 = bc2(FB * b2s * zs2), cB3 = bc2(FB * b3 * zs3);
    const u64 cB4 = bc2(FB * b4 * zs4), cB5 = bc2(FB * b5 * zs5);
    // 1 - e^{-y} = y*(1 - y/2 + y^2/6 - y^3/24 + y^4/120)
    const u64 cQ5 = bc2(8.3333333e-3f), cQ4 = bc2(-4.1666667e-2f);
    const u64 cQ3 = bc2(1.6666667e-1f), cQ2 = bc2(-0.5f);
    const u64 chL = bc2(hLf), chV = bc2(hVf);

    u64 accLr = 0, accLiP = 0, accVr = 0, accViN = 0;

    // front-end: u, omu, s4 chain, y = -dPa, Emn = 1 - e^{dPa}
    auto front = [&](u64 kf2, u64 rf2, u64 h2, u64 &u, u64 &omu, u64 &s4v, u64 &y, u64 &Emn) {
        u   = f2_(kf2, h2, cEPS);
        omu = f2_(rf2, h2, cEPS);
        u64 s2v = a2_(u, c1);
        u64 s3v = f2_(s2v, u, c1);
        s4v = f2_(s3v, u, c1);
        u64 s5v = f2_(s4v, u, c1);
        u64 sumA = f2_(cA5, s5v, f2_(cA4, s4v, f2_(cA3, s3v, f2_(cA2, s2v, cA1))));
        y = m2_(omu, sumA);
        u64 arg = m2_(y, cnL2);
        float alo, ahi; upk2(arg, alo, ahi);
        float exlo = ex2_(alo), exhi = ex2_(ahi);
        u64 h = f2_(y, cQ5, cQ4);
        h = f2_(h, y, cQ3);
        h = f2_(h, y, cQ2);
        h = f2_(h, y, c1);
        u64 ps = m2_(y, h);
        float pl, ph; upk2(ps, pl, ph);
        float el = (fabsf(alo) < 0.28853901f) ? pl : (1.0f - exlo);
        float eh = (fabsf(ahi) < 0.28853901f) ? ph : (1.0f - exhi);
        Emn = pk2(el, eh);
    };

    // packed principal csqrt of (wr, wi) -> sx2, sy2, rq2 = 1/|w|
    auto csq = [&](u64 wr, u64 wi, u64 &sx2, u64 &sy2, u64 &rq2) {
        u64 qq = f2_(wr, wr, m2_(wi, wi));
        float qqlo, qqhi; upk2(qq, qqlo, qqhi);
        rq2 = pk2(rsq_(qqlo), rsq_(qqhi));
        u64 mm = m2_(qq, rq2);
        u64 tt = m2_(cHalf, a2_(mm, abs2_(wr)));
        float ttlo, tthi; upk2(tt, ttlo, tthi);
        u64 itp = pk2(rsq_(ttlo), rsq_(tthi));
        u64 tb2 = m2_(tt, itp);
        u64 hy2 = m2_(m2_(wi, itp), cHalf);
        float wrlo, wrhi, tblo, tbhi, hylo, hyhi;
        upk2(wr, wrlo, wrhi); upk2(tb2, tblo, tbhi); upk2(hy2, hylo, hyhi);
        float sxlo, sylo, sxhi, syhi;
        if (wrlo >= 0.0f) { sxlo = tblo;         sylo = hylo; }
        else              { sxlo = fabsf(hylo);  sylo = copysignf(tblo, hylo); }
        if (wrhi >= 0.0f) { sxhi = tbhi;         syhi = hyhi; }
        else              { sxhi = fabsf(hyhi);  syhi = copysignf(tbhi, hyhi); }
        sx2 = pk2(sxlo, sxhi);
        sy2 = pk2(sylo, syhi);
    };

    // ---------------- L point pair ----------------
    auto Lpt = [&](int kLo, int kHi, float wLo, float wHi, bool gate) {
        u64 kf2 = pk2((float)kLo, (float)kHi);
        u64 rf2 = pk2((float)(NUL - 1 - kLo), (float)(NUL - 1 - kHi));
        u64 u, omu, s4v, y, Emn;
        front(kf2, rf2, chL, u, omu, s4v, y, Emn);

        u64 u2v = m2_(u, u);
        u64 u4v = m2_(u2v, u2v);
        u64 z4  = m2_(cZS4, u4v);
        u64 omz4  = f2_(z4, cn1, c1);
        u64 omz4n = a2_(z4, cn1);

        u64 S  = m2_(cEPZ4, f2_(omz4n, Emn, m2_(omu, s4v)));  // zs^4 f(z) - z^4 f(zs)
        u64 sm = a2_(S, cnEPS);
        u64 R  = f2_(z4, cFZS, cEPS);
        u64 q  = f2_(R, R, cE2);
        u64 nre = f2_(sm, R, f2_(cEPS, q, cnE2));
        u64 Nv  = a2_(sm, R);
        u64 nim = m2_(cEPS, f2_(Nv, cn1, q));

        if (gate) {   // interior crossing sentinel: |D_re| < DELTA in coarse region
            float nl, nh, ql, qh;
            upk2(nre, nl, nh); upk2(q, ql, qh);
            if (fabsf(nl) < DELTA * ql || fabsf(nh) < DELTA * qh) sflag = 1;
        }

        u64 wr = m2_(omz4, nre);
        u64 wi = m2_(omz4, nim);
        u64 sx2, sy2, rq2;
        csq(wr, wi, sx2, sy2, rq2);

        u64 Pb2 = m2_(u, f2_(u, f2_(u, f2_(u, f2_(u, cB5, cB4), cB3), cB2), cB1));
        float pblo, pbhi; upk2(Pb2, pblo, pbhi);
        float qlo, qhi; upk2(q, qlo, qhi);
        u64 E2  = pk2(ex2_(pblo), ex2_(pbhi));
        u64 qs2 = m2_(q, pk2(rsq_(qlo), rsq_(qhi)));
        u64 rr2 = m2_(m2_(m2_(E2, qs2), rq2), pk2(wLo, wHi));

        accLr  = f2_(rr2, sx2, accLr);
        accLiP = f2_(rr2, sy2, accLiP);
    };

    // ---------------- V point pair ----------------
    auto Vpt = [&](int kLo, int kHi, float wLo, float wHi, bool gate) {
        u64 kf2 = pk2((float)kLo, (float)kHi);
        u64 rf2 = pk2((float)(NUV - 1 - kLo), (float)(NUV - 1 - kHi));
        u64 u, omu, s4v, y, Emn;
        front(kf2, rf2, chV, u, omu, s4v, y, Emn);

        u64 u2v = m2_(u, u);
        u64 u4v = m2_(u2v, u2v);
        u64 z2  = m2_(cZS2, u2v);
        u64 z4  = m2_(cZS4, u4v);
        u64 omz4n = a2_(z4, cn1);

        u64 S  = m2_(cEPZ4, f2_(omz4n, Emn, m2_(omu, s4v)));
        u64 sp = a2_(S, cEPS);
        u64 M  = m2_(z4, cFZS);
        u64 Rp = a2_(sp, M);
        u64 q  = f2_(Rp, Rp, cE2);
        u64 nre = f2_(Rp, sp, f2_(cEPS, q, cE2));
        u64 nim = m2_(cEPS, a2_(q, M));

        if (gate) {
            float nl, nh, ql, qh;
            upk2(nre, nl, nh); upk2(q, ql, qh);
            if (fabsf(nl) < DELTA * ql || fabsf(nh) < DELTA * qh) sflag = 1;
        }

        u64 sx2, sy2, rq2;
        csq(nre, nim, sx2, sy2, rq2);

        u64 Pb2  = m2_(u, f2_(u, f2_(u, f2_(u, f2_(u, cB5, cB4), cB3), cB2), cB1));
        u64 arg2 = f2_(y, cnHL2, a2_(Pb2, cHPA));
        float aglo, aghi; upk2(arg2, aglo, aghi);
        float qlo, qhi; upk2(q, qlo, qhi);
        u64 Ep2 = pk2(ex2_(aglo), ex2_(aghi));
        u64 qs2 = m2_(q, pk2(rsq_(qlo), rsq_(qhi)));
        u64 t2  = m2_(m2_(Ep2, qs2), rq2);

        u64 tre2 = f2_(t2, sx2, cn1);
        u64 tp2  = m2_(t2, sy2);                 // = -tim

        u64 cr2  = a2_(z2, cEPS);
        u64 crq2 = f2_(cr2, cr2, cE2);
        float cqlo, cqhi; upk2(crq2, cqlo, cqhi);
        u64 rc2 = pk2(rcp_(cqlo), rcp_(cqhi));
        u64 Ire2  = m2_(f2_(tre2, cr2, m2_(tp2, cnEPS)), rc2);
        u64 IimN2 = m2_(f2_(tp2, cr2, m2_(tre2, cEPS)), rc2);  // = -Iim

        u64 w2 = pk2(wLo, wHi);
        accVr  = f2_(w2, Ire2,  accVr);
        accViN = f2_(w2, IimN2, accViN);
    };

    // ================== composite (Richardson) pass ==================
    #pragma unroll 2
    for (int i = 0; i < 5; ++i) {
        int sLo = 2 * p + 256 * i;
        if (sLo < NSL) {
            int kLo, kHi; float wLo, wHi;
            mapL(sLo, kLo, wLo);
            mapL(sLo + 1, kHi, wHi);
            bool g = (sLo >= 16 && sLo <= SMEL);
            Lpt(kLo, kHi, wLo, wHi, g);
        }
    }
    #pragma unroll 2
    for (int i = 0; i < 4; ++i) {
        int sLo = 2 * p + 256 * i;
        if (sLo < NSV) {
            int kLo, kHi; float wLo, wHi;
            mapV(sLo, kLo, wLo);
            mapV(sLo + 1, kHi, wHi);
            bool g = (sLo >= 16 && sLo <= SMEV);
            Vpt(kLo, kHi, wLo, wHi, g);
        }
    }

    __syncthreads();   // flag visibility

    // ================== exact fine fallback (rare) ==================
    if (sflag) {
        accLr = 0; accLiP = 0; accVr = 0; accViN = 0;
        #pragma unroll 1
        for (int i = 0; i < 8; ++i) {
            int sLo = 2 * p + 256 * i;
            if (sLo < NUL) {
                int kLo, kHi; float wLo, wHi;
                mapFL(sLo, kLo, wLo);
                mapFL(sLo + 1, kHi, wHi);
                Lpt(kLo, kHi, wLo, wHi, false);
            }
        }
        #pragma unroll 1
        for (int i = 0; i < 6; ++i) {
            int sLo = 2 * p + 256 * i;
            if (sLo < NUV) {
                int kLo, kHi; float wLo, wHi;
                mapFV(sLo, kLo, wLo);
                mapFV(sLo + 1, kHi, wHi);
                Vpt(kLo, kHi, wLo, wHi, false);
            }
        }
    }

    // sum packed halves
    float lr0, lr1, li0, li1, vr0, vr1, vi0, vi1;
    upk2(accLr, lr0, lr1); upk2(accLiP, li0, li1);
    upk2(accVr, vr0, vr1); upk2(accViN, vi0, vi1);
    float aLr = lr0 + lr1, aLi = li0 + li1, aVr = vr0 + vr1, aVi = vi0 + vi1;

    #pragma unroll
    for (int o = 16; o > 0; o >>= 1) {
        aLr += __shfl_xor_sync(0xFFFFFFFFu, aLr, o);
        aLi += __shfl_xor_sync(0xFFFFFFFFu, aLi, o);
        aVr += __shfl_xor_sync(0xFFFFFFFFu, aVr, o);
        aVi += __shfl_xor_sync(0xFFFFFFFFu, aVi, o);
    }
    if (lane == 0) {
        red[w][0] = aLr;
        red[w][1] = -aLi;
        red[w][2] = aVr;
        red[w][3] = -aVi;
    }
    __syncthreads();

    if (threadIdx.x < 4) {
        const int c = threadIdx.x;
        const float v = red[0][c] + red[1][c] + red[2][c] + red[3][c];
        const float SLC = (float)((2.0 / M_PI) * ((1.0 - 2.0e-6) / (double)(NUL - 1)));
        const float SVC = (float)(2.0 * M_PI * ((1.0 - 2.0e-6) / (double)(NUV - 1)));
        const float TWO_PI = (float)(2.0 * M_PI);
        float r;
        if (c == 2)      r = fmaf(v, SVC * zsv, -(TWO_PI / zsv));
        else if (c == 3) r = v * (SVC * zsv);
        else             r = v * (SLC * zsv);
        out[c * B + zi] = r;
    }
}

extern "C" void kernel_launch(void* const* d_in, const int* in_sizes, int n_in,
                              void* d_out, int out_size)
{
    const float* a  = (const float*)d_in[0];
    const float* b  = (const float*)d_in[1];
    const float* zs = (const float*)d_in[2];
    float* out = (float*)d_out;
    const int B = in_sizes[2];

    adsbh_kernel<<<B, 128>>>(a, b, zs, out, B);
}

// round 16
// speedup vs baseline: 7.8243x; 1.6386x over previous
#include <cuda_runtime.h>
#include <math.h>

#define NUL 2000
#define NUV 1500
#define EPSF 1e-6f
#define EPS2 1e-12f
#define L2E 1.4426950408889634f

// Stride-4 composite layout. L: head k=0..15 | mid k=16..1920 step4 | tail k=1921..1999
//                            V: head k=0..15 | mid k=16..1456 step4 | tail k=1457..1499
// Weight sums verified == N-1 exactly (L: 15.5+1905+78.5=1999, V: 15.5+1441+42.5=1499).
#define SMEL4 492       // last middle slot L  (k=1920)
#define NSL4  572       // total L slots
#define SMEV4 376       // last middle slot V  (k=1456)
#define NSV4  420       // total V slots
#define W_SH  2.6666667f    // shared 8h-grid interior: 8/3
#define W_ON  5.3333335f    // 4h-only interior: 16/3
#define W_SEAM 1.8333334f   // seam: 4/3 + 1/2 = 11/6
#define DELTA 0.03f     // |D_re| flag threshold

typedef unsigned long long u64;

__device__ __forceinline__ u64 pk2(float lo, float hi){ u64 r; asm("mov.b64 %0,{%1,%2};" : "=l"(r) : "f"(lo), "f"(hi)); return r; }
__device__ __forceinline__ void upk2(u64 v, float &lo, float &hi){ asm("mov.b64 {%0,%1},%2;" : "=f"(lo), "=f"(hi) : "l"(v)); }
__device__ __forceinline__ u64 bc2(float x){ return pk2(x, x); }
__device__ __forceinline__ u64 f2_(u64 a, u64 b, u64 c){ u64 d; asm("fma.rn.f32x2 %0,%1,%2,%3;" : "=l"(d) : "l"(a), "l"(b), "l"(c)); return d; }
__device__ __forceinline__ u64 m2_(u64 a, u64 b){ u64 d; asm("mul.rn.f32x2 %0,%1,%2;" : "=l"(d) : "l"(a), "l"(b)); return d; }
__device__ __forceinline__ u64 a2_(u64 a, u64 b){ u64 d; asm("add.rn.f32x2 %0,%1,%2;" : "=l"(d) : "l"(a), "l"(b)); return d; }
__device__ __forceinline__ u64 abs2_(u64 a){ u64 d; asm("and.b64 %0,%1,0x7FFFFFFF7FFFFFFF;" : "=l"(d) : "l"(a)); return d; }

__device__ __forceinline__ float rsq_(float x){ float r; asm("rsqrt.approx.f32 %0,%1;" : "=f"(r) : "f"(x)); return r; }
__device__ __forceinline__ float rcp_(float x){ float r; asm("rcp.approx.f32 %0,%1;" : "=f"(r) : "f"(x)); return r; }
__device__ __forceinline__ float ex2_(float x){ float r; asm("ex2.approx.f32 %0,%1;" : "=f"(r) : "f"(x)); return r; }

// slot -> (float k, weight); stride-4 composite
__device__ __forceinline__ void mapL4(int s, float &kf, float &w) {
    float sf = (float)s;
    if (s < 16)         { kf = sf; w = (s == 0) ? 0.5f : 1.0f; }
    else if (s <= SMEL4){ kf = fmaf(sf, 4.0f, -48.0f);
                          w = (s == 16 || s == SMEL4) ? W_SEAM : ((s & 1) ? W_ON : W_SH); }
    else if (s < NSL4)  { kf = sf + 1428.0f; w = (s == NSL4 - 1) ? 0.5f : 1.0f; }
    else                { kf = 100.0f; w = 0.0f; }
}
__device__ __forceinline__ void mapV4(int s, float &kf, float &w) {
    float sf = (float)s;
    if (s < 16)         { kf = sf; w = (s == 0) ? 0.5f : 1.0f; }
    else if (s <= SMEV4){ kf = fmaf(sf, 4.0f, -48.0f);
                          w = (s == 16 || s == SMEV4) ? W_SEAM : ((s & 1) ? W_ON : W_SH); }
    else if (s < NSV4)  { kf = sf + 1080.0f; w = (s == NSV4 - 1) ? 0.5f : 1.0f; }
    else                { kf = 100.0f; w = 0.0f; }
}
// plain fine trapezoid maps (fallback path)
__device__ __forceinline__ void mapFL(int s, float &kf, float &w) {
    kf = (float)((s < NUL) ? s : (NUL - 1));
    w = (s >= NUL) ? 0.0f : ((s == 0 || s == NUL - 1) ? 0.5f : 1.0f);
}
__device__ __forceinline__ void mapFV(int s, float &kf, float &w) {
    kf = (float)((s < NUV) ? s : (NUV - 1));
    w = (s >= NUV) ? 0.0f : ((s == 0 || s == NUV - 1) ? 0.5f : 1.0f);
}

__global__ void __launch_bounds__(128, 7)
adsbh_kernel(const float* __restrict__ A,
             const float* __restrict__ Bc,
             const float* __restrict__ ZS,
             float* __restrict__ out, int B)
{
    __shared__ float red[4][4];
    __shared__ int sflag;

    const int w    = threadIdx.x >> 5;
    const int lane = threadIdx.x & 31;
    const int p    = lane + 32 * w;       // pair index 0..127
    const int zi   = blockIdx.x;

    if (threadIdx.x == 0) sflag = 0;
    __syncthreads();

    const float a1 = A[0], a2s = A[1], a3 = A[2], a4 = A[3], a5 = A[4];
    const float b1 = Bc[0], b2s = Bc[1], b3 = Bc[2], b4 = Bc[3], b5 = Bc[4];

    const float hLf = (float)((1.0 - 2.0e-6) / (double)(NUL - 1));
    const float hVf = (float)((1.0 - 2.0e-6) / (double)(NUV - 1));

    const float zsv = ZS[zi];
    const float zs2 = zsv * zsv;
    const float zs3 = zs2 * zsv;
    const float zs4 = zs2 * zs2;
    const float zs5 = zs4 * zsv;

    const float Pazs   = zsv * fmaf(zsv, fmaf(zsv, fmaf(zsv, fmaf(zsv, a5, a4), a3), a2s), a1);
    const float e_pazs = expf(Pazs);
    const float fzsv   = (1.0f - zs4) * e_pazs;
    const float epz4v  = e_pazs * zs4;

    const u64 c1    = bc2(1.0f);
    const u64 cn1   = bc2(-1.0f);
    const u64 cHalf = bc2(0.5f);
    const u64 cEPS  = bc2(EPSF);
    const u64 cnEPS = bc2(-EPSF);
    const u64 cE2   = bc2(EPS2);
    const u64 cnE2  = bc2(-EPS2);
    const u64 cnL2  = bc2(-L2E);
    const u64 cnHL2 = bc2(-0.5f * L2E);
    const u64 cHPA  = bc2(0.5f * L2E * Pazs);
    const u64 cZS2  = bc2(zs2);
    const u64 cZS4  = bc2(zs4);
    const u64 cEPZ4 = bc2(epz4v);
    const u64 cFZS  = bc2(fzsv);
    const u64 cNL1  = bc2((float)(NUL - 1));
    const u64 cNV1  = bc2((float)(NUV - 1));
    const u64 cA1 = bc2(a1 * zsv), cA2 = bc2(a2s * zs2), cA3 = bc2(a3 * zs3);
    const u64 cA4 = bc2(a4 * zs4), cA5 = bc2(a5 * zs5);
    const float FB = 0.5f * L2E;   // exp(0.5*Pb) = ex2(FB*Pb)
    const u64 cB1 = bc2(FB * b1 * zsv), cB2 = bc2(FB * b2s * zs2), cB3 = bc2(FB * b3 * zs3);
    const u64 cB4 = bc2(FB * b4 * zs4), cB5 = bc2(FB * b5 * zs5);
    // 1 - e^{-y} = y*(1 - y/2 + y^2/6 - y^3/24 + y^4/120)
    const u64 cQ5 = bc2(8.3333333e-3f), cQ4 = bc2(-4.1666667e-2f);
    const u64 cQ3 = bc2(1.6666667e-1f), cQ2 = bc2(-0.5f);
    const u64 chL = bc2(hLf), chV = bc2(hVf);

    u64 accLr = 0, accLiP = 0, accVr = 0, accViN = 0;

    // front-end: u, omu, s4 chain, y = -dPa, Emn = 1 - e^{dPa}
    auto front = [&](u64 kf2, u64 rf2, u64 h2, u64 &u, u64 &omu, u64 &s4v, u64 &y, u64 &Emn) {
        u   = f2_(kf2, h2, cEPS);
        omu = f2_(rf2, h2, cEPS);
        u64 s2v = a2_(u, c1);
        u64 s3v = f2_(s2v, u, c1);
        s4v = f2_(s3v, u, c1);
        u64 s5v = f2_(s4v, u, c1);
        u64 sumA = f2_(cA5, s5v, f2_(cA4, s4v, f2_(cA3, s3v, f2_(cA2, s2v, cA1))));
        y = m2_(omu, sumA);
        u64 arg = m2_(y, cnL2);
        float alo, ahi; upk2(arg, alo, ahi);
        float exlo = ex2_(alo), exhi = ex2_(ahi);
        u64 h = f2_(y, cQ5, cQ4);
        h = f2_(h, y, cQ3);
        h = f2_(h, y, cQ2);
        h = f2_(h, y, c1);
        u64 ps = m2_(y, h);
        float pl, ph; upk2(ps, pl, ph);
        float el = (fabsf(alo) < 0.28853901f) ? pl : (1.0f - exlo);
        float eh = (fabsf(ahi) < 0.28853901f) ? ph : (1.0f - exhi);
        Emn = pk2(el, eh);
    };

    // packed principal csqrt of (wr, wi) -> sx2, sy2, rq2 = 1/|w|
    auto csq = [&](u64 wr, u64 wi, u64 &sx2, u64 &sy2, u64 &rq2) {
        u64 qq = f2_(wr, wr, m2_(wi, wi));
        float qqlo, qqhi; upk2(qq, qqlo, qqhi);
        rq2 = pk2(rsq_(qqlo), rsq_(qqhi));
        u64 mm = m2_(qq, rq2);
        u64 tt = m2_(cHalf, a2_(mm, abs2_(wr)));
        float ttlo, tthi; upk2(tt, ttlo, tthi);
        u64 itp = pk2(rsq_(ttlo), rsq_(tthi));
        u64 tb2 = m2_(tt, itp);
        u64 hy2 = m2_(m2_(wi, itp), cHalf);
        float wrlo, wrhi, tblo, tbhi, hylo, hyhi;
        upk2(wr, wrlo, wrhi); upk2(tb2, tblo, tbhi); upk2(hy2, hylo, hyhi);
        float sxlo, sylo, sxhi, syhi;
        if (wrlo >= 0.0f) { sxlo = tblo;         sylo = hylo; }
        else              { sxlo = fabsf(hylo);  sylo = copysignf(tblo, hylo); }
        if (wrhi >= 0.0f) { sxhi = tbhi;         syhi = hyhi; }
        else              { sxhi = fabsf(hyhi);  syhi = copysignf(tbhi, hyhi); }
        sx2 = pk2(sxlo, sxhi);
        sy2 = pk2(sylo, syhi);
    };

    // ---------------- L point pair ----------------
    auto Lpt = [&](float kLo, float kHi, float wLo, float wHi, bool gate) {
        u64 kf2 = pk2(kLo, kHi);
        u64 rf2 = f2_(kf2, cn1, cNL1);     // (NUL-1) - k
        u64 u, omu, s4v, y, Emn;
        front(kf2, rf2, chL, u, omu, s4v, y, Emn);

        u64 u2v = m2_(u, u);
        u64 u4v = m2_(u2v, u2v);
        u64 z4  = m2_(cZS4, u4v);
        u64 omz4  = f2_(z4, cn1, c1);
        u64 omz4n = a2_(z4, cn1);

        u64 S  = m2_(cEPZ4, f2_(omz4n, Emn, m2_(omu, s4v)));  // zs^4 f(z) - z^4 f(zs)
        u64 sm = a2_(S, cnEPS);
        u64 R  = f2_(z4, cFZS, cEPS);
        u64 q  = f2_(R, R, cE2);
        u64 nre = f2_(sm, R, f2_(cEPS, q, cnE2));
        u64 Nv  = a2_(sm, R);
        u64 nim = m2_(cEPS, f2_(Nv, cn1, q));

        if (gate) {   // interior crossing sentinel: |D_re| < DELTA in coarse region
            float nl, nh, ql, qh;
            upk2(nre, nl, nh); upk2(q, ql, qh);
            if (fabsf(nl) < DELTA * ql || fabsf(nh) < DELTA * qh) sflag = 1;
        }

        u64 wr = m2_(omz4, nre);
        u64 wi = m2_(omz4, nim);
        u64 sx2, sy2, rq2;
        csq(wr, wi, sx2, sy2, rq2);

        u64 Pb2 = m2_(u, f2_(u, f2_(u, f2_(u, f2_(u, cB5, cB4), cB3), cB2), cB1));
        float pblo, pbhi; upk2(Pb2, pblo, pbhi);
        float qlo, qhi; upk2(q, qlo, qhi);
        u64 E2  = pk2(ex2_(pblo), ex2_(pbhi));
        u64 qs2 = m2_(q, pk2(rsq_(qlo), rsq_(qhi)));
        u64 rr2 = m2_(m2_(m2_(E2, qs2), rq2), pk2(wLo, wHi));

        accLr  = f2_(rr2, sx2, accLr);
        accLiP = f2_(rr2, sy2, accLiP);
    };

    // ---------------- V point pair ----------------
    auto Vpt = [&](float kLo, float kHi, float wLo, float wHi, bool gate) {
        u64 kf2 = pk2(kLo, kHi);
        u64 rf2 = f2_(kf2, cn1, cNV1);     // (NUV-1) - k
        u64 u, omu, s4v, y, Emn;
        front(kf2, rf2, chV, u, omu, s4v, y, Emn);

        u64 u2v = m2_(u, u);
        u64 u4v = m2_(u2v, u2v);
        u64 z2  = m2_(cZS2, u2v);
        u64 z4  = m2_(cZS4, u4v);
        u64 omz4n = a2_(z4, cn1);

        u64 S  = m2_(cEPZ4, f2_(omz4n, Emn, m2_(omu, s4v)));
        u64 sp = a2_(S, cEPS);
        u64 M  = m2_(z4, cFZS);
        u64 Rp = a2_(sp, M);
        u64 q  = f2_(Rp, Rp, cE2);
        u64 nre = f2_(Rp, sp, f2_(cEPS, q, cE2));
        u64 nim = m2_(cEPS, a2_(q, M));

        if (gate) {
            float nl, nh, ql, qh;
            upk2(nre, nl, nh); upk2(q, ql, qh);
            if (fabsf(nl) < DELTA * ql || fabsf(nh) < DELTA * qh) sflag = 1;
        }

        u64 sx2, sy2, rq2;
        csq(nre, nim, sx2, sy2, rq2);

        u64 Pb2  = m2_(u, f2_(u, f2_(u, f2_(u, f2_(u, cB5, cB4), cB3), cB2), cB1));
        u64 arg2 = f2_(y, cnHL2, a2_(Pb2, cHPA));
        float aglo, aghi; upk2(arg2, aglo, aghi);
        float qlo, qhi; upk2(q, qlo, qhi);
        u64 Ep2 = pk2(ex2_(aglo), ex2_(aghi));
        u64 qs2 = m2_(q, pk2(rsq_(qlo), rsq_(qhi)));
        u64 t2  = m2_(m2_(Ep2, qs2), rq2);

        u64 tre2 = f2_(t2, sx2, cn1);
        u64 tp2  = m2_(t2, sy2);                 // = -tim

        u64 cr2  = a2_(z2, cEPS);
        u64 crq2 = f2_(cr2, cr2, cE2);
        float cqlo, cqhi; upk2(crq2, cqlo, cqhi);
        u64 rc2 = pk2(rcp_(cqlo), rcp_(cqhi));
        u64 Ire2  = m2_(f2_(tre2, cr2, m2_(tp2, cnEPS)), rc2);
        u64 IimN2 = m2_(f2_(tp2, cr2, m2_(tre2, cEPS)), rc2);  // = -Iim

        u64 w2 = pk2(wLo, wHi);
        accVr  = f2_(w2, Ire2,  accVr);
        accViN = f2_(w2, IimN2, accViN);
    };

    // ================== stride-4 composite pass ==================
    #pragma unroll
    for (int i = 0; i < 3; ++i) {
        int sLo = 2 * p + 256 * i;
        if (sLo < NSL4) {
            float kLo, kHi, wLo, wHi;
            mapL4(sLo, kLo, wLo);
            mapL4(sLo + 1, kHi, wHi);
            bool g = (sLo >= 16 && sLo <= SMEL4);
            Lpt(kLo, kHi, wLo, wHi, g);
        }
    }
    #pragma unroll
    for (int i = 0; i < 2; ++i) {
        int sLo = 2 * p + 256 * i;
        if (sLo < NSV4) {
            float kLo, kHi, wLo, wHi;
            mapV4(sLo, kLo, wLo);
            mapV4(sLo + 1, kHi, wHi);
            bool g = (sLo >= 16 && sLo <= SMEV4);
            Vpt(kLo, kHi, wLo, wHi, g);
        }
    }

    __syncthreads();   // flag visibility

    // ================== exact fine fallback (rare) ==================
    if (sflag) {
        accLr = 0; accLiP = 0; accVr = 0; accViN = 0;
        #pragma unroll 1
        for (int i = 0; i < 8; ++i) {
            int sLo = 2 * p + 256 * i;
            if (sLo < NUL) {
                float kLo, kHi, wLo, wHi;
                mapFL(sLo, kLo, wLo);
                mapFL(sLo + 1, kHi, wHi);
                Lpt(kLo, kHi, wLo, wHi, false);
            }
        }
        #pragma unroll 1
        for (int i = 0; i < 6; ++i) {
            int sLo = 2 * p + 256 * i;
            if (sLo < NUV) {
                float kLo, kHi, wLo, wHi;
                mapFV(sLo, kLo, wLo);
                mapFV(sLo + 1, kHi, wHi);
                Vpt(kLo, kHi, wLo, wHi, false);
            }
        }
    }

    // sum packed halves
    float lr0, lr1, li0, li1, vr0, vr1, vi0, vi1;
    upk2(accLr, lr0, lr1); upk2(accLiP, li0, li1);
    upk2(accVr, vr0, vr1); upk2(accViN, vi0, vi1);
    float aLr = lr0 + lr1, aLi = li0 + li1, aVr = vr0 + vr1, aVi = vi0 + vi1;

    #pragma unroll
    for (int o = 16; o > 0; o >>= 1) {
        aLr += __shfl_xor_sync(0xFFFFFFFFu, aLr, o);
        aLi += __shfl_xor_sync(0xFFFFFFFFu, aLi, o);
        aVr += __shfl_xor_sync(0xFFFFFFFFu, aVr, o);
        aVi += __shfl_xor_sync(0xFFFFFFFFu, aVi, o);
    }
    if (lane == 0) {
        red[w][0] = aLr;
        red[w][1] = -aLi;
        red[w][2] = aVr;
        red[w][3] = -aVi;
    }
    __syncthreads();

    if (threadIdx.x < 4) {
        const int c = threadIdx.x;
        const float v = red[0][c] + red[1][c] + red[2][c] + red[3][c];
        const float SLC = (float)((2.0 / M_PI) * ((1.0 - 2.0e-6) / (double)(NUL - 1)));
        const float SVC = (float)(2.0 * M_PI * ((1.0 - 2.0e-6) / (double)(NUV - 1)));
        const float TWO_PI = (float)(2.0 * M_PI);
        float r;
        if (c == 2)      r = fmaf(v, SVC * zsv, -(TWO_PI / zsv));
        else if (c == 3) r = v * (SVC * zsv);
        else             r = v * (SLC * zsv);
        out[c * B + zi] = r;
    }
}

extern "C" void kernel_launch(void* const* d_in, const int* in_sizes, int n_in,
                              void* d_out, int out_size)
{
    const float* a  = (const float*)d_in[0];
    const float* b  = (const float*)d_in[1];
    const float* zs = (const float*)d_in[2];
    float* out = (float*)d_out;
    const int B = in_sizes[2];

    adsbh_kernel<<<B, 128>>>(a, b, zs, out, B);
}